// round 14
// baseline (speedup 1.0000x reference)
#include <cuda_runtime.h>
#include <cuda_fp16.h>
#include <cstdint>

#define EGO   64
#define MEM   128
#define NOBJ  20
#define HW    65536     // 256*256
#define NPIX  131072    // 2 * HW
#define NB    2
#define TT    4

typedef unsigned long long u64;

// ---------------- packed f32x2 helpers ----------------
__device__ __forceinline__ u64 bcast2(float x) {
    u64 r; asm("mov.b64 %0, {%1, %1};" : "=l"(r) : "f"(x)); return r;
}
__device__ __forceinline__ u64 pack2f(float x, float y) {
    u64 r; asm("mov.b64 %0, {%1, %2};" : "=l"(r) : "f"(x), "f"(y)); return r;
}
__device__ __forceinline__ u64 ffma2(u64 a, u64 b, u64 c) {
    u64 d; asm("fma.rn.f32x2 %0, %1, %2, %3;" : "=l"(d) : "l"(a), "l"(b), "l"(c)); return d;
}
__device__ __forceinline__ float2 unpk(u64 a) {
    float2 f; asm("mov.b64 {%0, %1}, %2;" : "=f"(f.x), "=f"(f.y) : "l"(a)); return f;
}

// ---------------- fast transcendentals ----------------
__device__ __forceinline__ float fast_sigmoid(float x) {
    float e; asm("ex2.approx.f32 %0, %1;" : "=f"(e) : "f"(-1.4426950408889634f * x));
    float r; asm("rcp.approx.f32 %0, %1;" : "=f"(r) : "f"(1.f + e));
    return r;
}
__device__ __forceinline__ float fast_tanh(float x) {
    float e; asm("ex2.approx.f32 %0, %1;" : "=f"(e) : "f"(2.8853900817779268f * x));
    float r; asm("rcp.approx.f32 %0, %1;" : "=f"(r) : "f"(1.f + e));
    return 1.f - 2.f * r;
}

// ---------------- smem / swizzle / mma / cp.async helpers ----------------
__device__ __forceinline__ uint32_t smem_u32(const void* p) {
    uint32_t a; asm("{ .reg .u64 t; cvta.to.shared.u64 t, %1; cvt.u32.u64 %0, t; }" : "=r"(a) : "l"(p));
    return a;
}
#define SW128(o) ((o) ^ (((o) >> 3) & 0x70))

__device__ __forceinline__ void ldsm_x4(uint32_t& r0, uint32_t& r1, uint32_t& r2, uint32_t& r3,
                                        uint32_t addr) {
    asm volatile("ldmatrix.sync.aligned.m8n8.x4.shared.b16 {%0,%1,%2,%3}, [%4];"
                 : "=r"(r0), "=r"(r1), "=r"(r2), "=r"(r3) : "r"(addr));
}
__device__ __forceinline__ void mma16816(float* c, const uint32_t* a, uint32_t b0, uint32_t b1) {
    asm volatile(
        "mma.sync.aligned.m16n8k16.row.col.f32.f16.f16.f32 "
        "{%0,%1,%2,%3}, {%4,%5,%6,%7}, {%8,%9}, {%0,%1,%2,%3};"
        : "+f"(c[0]), "+f"(c[1]), "+f"(c[2]), "+f"(c[3])
        : "r"(a[0]), "r"(a[1]), "r"(a[2]), "r"(a[3]), "r"(b0), "r"(b1));
}
__device__ __forceinline__ void cp16(uint32_t dst, const void* src) {
    asm volatile("cp.async.cg.shared.global [%0], [%1], 16;" :: "r"(dst), "l"(src));
}
__device__ __forceinline__ void cp16z(uint32_t dst, const void* src, int sz) {
    asm volatile("cp.async.cg.shared.global [%0], [%1], 16, %2;" :: "r"(dst), "l"(src), "r"(sz));
}
#define CP_COMMIT() asm volatile("cp.async.commit_group;" ::: "memory")
#define CP_WAIT(n)  asm volatile("cp.async.wait_group %0;" :: "n"(n) : "memory")

// ---------------- static scratch ----------------
__device__ __half g_hA[(size_t)NPIX * 128];
__device__ __half g_hB[(size_t)NPIX * 128];
__device__ __half g_f16[(size_t)NPIX * TT * 64];  // fp16 features
__device__ __half g_act16[(size_t)NPIX * 256];
__device__ float  g_bufA[(size_t)NPIX * 128];
__device__ float  g_bufB[(size_t)NPIX * 128];
__device__ __half g_w16[49 * 128 * 128];         // conv1
__device__ __half g_w16b[300000];                // conv2 @0, conv3 @147456, obj1 @221184
__device__ __half g_w16g[4 * 3 * 128 * 64];      // GRU
__device__ int    g_any[8];
__device__ float  g_stats[1024];                 // 4 segments of 256

// ---------------- any / observed ----------------
__global__ void any_kernel(const int* __restrict__ masks) {
    int idx = blockIdx.x * blockDim.x + threadIdx.x;
    int v = masks[idx];
    unsigned b = __ballot_sync(0xffffffffu, v > 0);
    if ((threadIdx.x & 31) == 0 && b)
        atomicOr(&g_any[idx >> 16], 1);
}
__global__ void obs_kernel(const int* __restrict__ masks, float* __restrict__ outobs) {
    int idx = blockIdx.x * blockDim.x + threadIdx.x;
    int n = idx >> 16, pix = idx & 65535;
    int s = 0;
#pragma unroll
    for (int t = 0; t < TT; ++t)
        s += masks[((n * TT + t) << 16) + pix] * g_any[n * TT + t];
    outobs[idx] = (float)s;
}

// ---------------- feats fp32 -> fp16 ----------------
__global__ void f16feat(const float* __restrict__ in, __half* __restrict__ out) {
    size_t i = ((size_t)blockIdx.x * 256 + threadIdx.x) * 8;
    float4 a = *(const float4*)(in + i);
    float4 b = *(const float4*)(in + i + 4);
    __half2 h[4] = { __floats2half2_rn(a.x, a.y), __floats2half2_rn(a.z, a.w),
                     __floats2half2_rn(b.x, b.y), __floats2half2_rn(b.z, b.w) };
    *(uint4*)(out + i) = *(const uint4*)h;
}

// ---------------- GRU weight prep (gate-grouped columns) ----------------
__global__ void w16gru_prep(const float* __restrict__ wih, const float* __restrict__ whh,
                            __half* __restrict__ o) {
    int i = blockIdx.x * 256 + threadIdx.x;
    if (i >= 4 * 3 * 128 * 64) return;
    int bb = i / 24576; int r = i - bb * 24576;
    int c  = r / 8192;  int r2 = r - c * 8192;
    int row = r2 >> 6;  int kk = r2 & 63;
    int g4 = row >> 5, ul = row & 31;
    int gu = bb * 32 + ul;
    float v = 0.f;
    if (g4 == 0)      v = (c == 0) ? wih[(      gu) * 64 + kk] : whh[(      gu) * 128 + (c - 1) * 64 + kk];
    else if (g4 == 1) v = (c == 0) ? wih[(128 + gu) * 64 + kk] : whh[(128 + gu) * 128 + (c - 1) * 64 + kk];
    else if (g4 == 2) v = (c == 0) ? wih[(256 + gu) * 64 + kk] : 0.f;
    else              v = (c == 0) ? 0.f : whh[(256 + gu) * 128 + (c - 1) * 64 + kk];
    o[i] = __float2half_rn(v);
}

// ---------------- GRU step via HMMA (R13: cp.async pre-stage, zero-sync) -----
#define GRU_SMEM (98304 + 768 + 32 + 512 + 512)

template<bool FIRST>
__global__ __launch_bounds__(256, 2) void gru_hmma(
    const __half* __restrict__ f16, const int* __restrict__ masks,
    const __half* __restrict__ w16g,
    const float* __restrict__ b_ih, const float* __restrict__ b_hh,
    const __half* __restrict__ hin, __half* __restrict__ hout, int t)
{
    extern __shared__ char sm[];
    float* gbuf = (float*)sm;
    float* sbias = (float*)(sm + 98304);
    int* wcnt  = (int*)(sm + 98304 + 768);
    int* cnts  = (int*)(sm + 98304 + 768 + 16);
    int* clist = (int*)(sm + 98304 + 768 + 32);
    int* ulist = (int*)(sm + 98304 + 768 + 32 + 512);

    int tid = threadIdx.x;
    int lane = tid & 31, wrp = tid >> 5;
    int mw = wrp >> 1, nw = wrp & 1;
    int p0 = blockIdx.x * 128;
    int bb = blockIdx.y;
    int ub = bb * 32;
    int n = p0 >> 16, pix0 = p0 & 65535;
    uint32_t sbase = smem_u32(sm);

    const int* mrow = masks + ((size_t)(n * TT + t) << 16) + pix0;

    const int CH = FIRST ? 1 : 3;
    int px = tid >> 1, sg = tid & 1;

    // ---- stage everything via cp.async ----
    {
        int sr = tid >> 1, h2 = tid & 1;
#pragma unroll
        for (int c = 0; c < 3; ++c) {
            if (c >= CH) break;
            const __half* src = w16g + ((size_t)((bb * 3 + c) * 128 + sr)) * 64 + h2 * 32;
            uint32_t base = sbase + 49152 + c * 16384;
#pragma unroll
            for (int j = 0; j < 4; ++j) {
                uint32_t bo = (uint32_t)sr * 128 + h2 * 64 + j * 16;
                cp16(base + SW128(bo), src + j * 8);
            }
        }
    }
    {
        const __half* src = f16 + ((size_t)(n * TT + t) * HW + pix0 + px) * 64 + sg * 32;
#pragma unroll
        for (int j = 0; j < 4; ++j) {
            uint32_t bo = (uint32_t)px * 128 + sg * 64 + j * 16;
            cp16(sbase + SW128(bo), src + j * 8);
        }
    }
    if (!FIRST) {
#pragma unroll
        for (int c = 1; c < 3; ++c) {
            const __half* src = hin + ((size_t)(p0 + px)) * 128 + (c - 1) * 64 + sg * 32;
            uint32_t base = sbase + c * 16384;
#pragma unroll
            for (int j = 0; j < 4; ++j) {
                uint32_t bo = (uint32_t)px * 128 + sg * 64 + j * 16;
                cp16(base + SW128(bo), src + j * 8);
            }
        }
    }
    CP_COMMIT();

    int mv = 0; int posm = 0;
    if (tid < 128) {
        mv = mrow[tid] > 0;
        unsigned bal = __ballot_sync(0xffffffffu, mv);
        posm = __popc(bal & ((1u << lane) - 1));
        if (lane == 0) wcnt[tid >> 5] = __popc(bal);
    }
    if (tid < 96) {
        int g = tid >> 5, u = tid & 31;
        sbias[tid] = b_ih[g * 128 + ub + u];
    } else if (tid < 192) {
        int t2 = tid - 96;
        int g = t2 >> 5, u = t2 & 31;
        sbias[tid] = b_hh[g * 128 + ub + u];
    }

    CP_WAIT(0);
    __syncthreads();
    if (tid < 128) {
        int w = tid >> 5;
        int off = 0;
#pragma unroll
        for (int j = 0; j < 4; ++j) if (j < w) off += wcnt[j];
        if (mv) clist[off + posm] = tid;
        else    ulist[32 * w - off + lane - posm] = tid;
        if (tid == 0) cnts[0] = wcnt[0] + wcnt[1] + wcnt[2] + wcnt[3];
    }

    float acc[2][8][4];
#pragma unroll
    for (int mi = 0; mi < 2; ++mi)
#pragma unroll
        for (int nj = 0; nj < 8; ++nj)
#pragma unroll
            for (int e = 0; e < 4; ++e) acc[mi][nj][e] = 0.f;

#pragma unroll
    for (int c = 0; c < 3; ++c) {
        if (c >= CH) break;
        uint32_t abase = sbase + c * 16384;
        uint32_t bbase = sbase + 49152 + c * 16384;
#pragma unroll
        for (int kk = 0; kk < 4; ++kk) {
            uint32_t bo = kk * 32 + ((lane >> 4) << 4);
            uint32_t afr[2][4];
#pragma unroll
            for (int mi = 0; mi < 2; ++mi) {
                uint32_t row = mw * 32 + mi * 16 + (lane & 15);
                ldsm_x4(afr[mi][0], afr[mi][1], afr[mi][2], afr[mi][3],
                        abase + SW128(row * 128 + bo));
            }
            auto dob = [&](int ni) {
                uint32_t row = nw * 64 + ni * 16 + (lane & 15);
                uint32_t b0, b1, b2, b3;
                ldsm_x4(b0, b1, b2, b3, bbase + SW128(row * 128 + bo));
#pragma unroll
                for (int mi = 0; mi < 2; ++mi) {
                    mma16816(acc[mi][ni * 2],     afr[mi], b0, b2);
                    mma16816(acc[mi][ni * 2 + 1], afr[mi], b1, b3);
                }
            };
            if (nw == 0) { dob(0); dob(1); dob(2); dob(3); }
            else if (c == 0) { dob(0); dob(1); }
            else { dob(2); dob(3); }
        }
    }
    __syncthreads();

#pragma unroll
    for (int mi = 0; mi < 2; ++mi)
#pragma unroll
        for (int nj = 0; nj < 8; ++nj) {
            int row = mw * 32 + mi * 16 + (lane >> 2);
            int col = nw * 64 + nj * 8 + (lane & 3) * 2;
            *(float2*)&gbuf[row * 132 + col]       = make_float2(acc[mi][nj][0], acc[mi][nj][1]);
            *(float2*)&gbuf[(row + 8) * 132 + col] = make_float2(acc[mi][nj][2], acc[mi][nj][3]);
        }
    __syncthreads();

    int cnt = cnts[0];
    for (int i = tid; i < 2 * cnt; i += 256) {
        int pxl = clist[i >> 1];
        int half = i & 1;
        __half hold[16];
        if (!FIRST) {
            const __half* hp = hin + ((size_t)(p0 + pxl)) * 128 + ub + half * 16;
            *(uint4*)&hold[0] = *(const uint4*)hp;
            *(uint4*)&hold[8] = *(const uint4*)(hp + 8);
        }
        __half hnew[16];
#pragma unroll
        for (int ug = 0; ug < 4; ++ug) {
            int cb = half * 16 + ug * 4;
            float4 rr = *(float4*)&gbuf[pxl * 132 + cb];
            float4 zz = *(float4*)&gbuf[pxl * 132 + 32 + cb];
            float4 xx = *(float4*)&gbuf[pxl * 132 + 64 + cb];
            float4 hh4 = *(float4*)&gbuf[pxl * 132 + 96 + cb];
            float rv[4] = { rr.x, rr.y, rr.z, rr.w };
            float zv[4] = { zz.x, zz.y, zz.z, zz.w };
            float xv[4] = { xx.x, xx.y, xx.z, xx.w };
            float hv4[4] = { hh4.x, hh4.y, hh4.z, hh4.w };
#pragma unroll
            for (int e = 0; e < 4; ++e) {
                int ul = cb + e;
                float r = fast_sigmoid(rv[e] + sbias[ul] + sbias[96 + ul]);
                float z = fast_sigmoid(zv[e] + sbias[32 + ul] + sbias[128 + ul]);
                float nv = fast_tanh(xv[e] + sbias[64 + ul] + r * (hv4[e] + sbias[160 + ul]));
                float ho = FIRST ? 0.f : __half2float(hold[ug * 4 + e]);
                float hv = nv + z * (ho - nv);
                hnew[ug * 4 + e] = __float2half_rn(hv);
            }
        }
        __half* op = hout + ((size_t)(p0 + pxl)) * 128 + ub + half * 16;
        *(uint4*)op       = *(const uint4*)&hnew[0];
        *(uint4*)(op + 8) = *(const uint4*)&hnew[8];
    }
    int un = 128 - cnt;
    for (int i = tid; i < 2 * un; i += 256) {
        int pxl = ulist[i >> 1];
        int half = i & 1;
        __half* op = hout + ((size_t)(p0 + pxl)) * 128 + ub + half * 16;
        if (FIRST) {
            uint4 z = make_uint4(0, 0, 0, 0);
            *(uint4*)op = z; *(uint4*)(op + 8) = z;
        } else {
            const __half* hp = hin + ((size_t)(p0 + pxl)) * 128 + ub + half * 16;
            *(uint4*)op       = *(const uint4*)hp;
            *(uint4*)(op + 8) = *(const uint4*)(hp + 8);
        }
    }
}

// ---------------- bn+relu (in-kernel bnfin) f32 -> hi/lo fp16 ----------------
template<int CIN, int CHI>
__global__ void bnrelu_hl(const float* __restrict__ in, __half* __restrict__ out,
                          const float* __restrict__ g, const float* __restrict__ b,
                          const float* __restrict__ stats) {
    __shared__ float ss[CIN], sh[CIN];
    int tid = threadIdx.x;
    if (tid < CIN) {
        float inv = 1.f / (float)NPIX;
        float mu  = stats[tid] * inv;
        float var = stats[128 + tid] * inv - mu * mu;
        float sc  = g[tid] * rsqrtf(var + 1e-5f);
        ss[tid] = sc;
        sh[tid] = b[tid] - mu * sc;
    }
    __syncthreads();

    int i = blockIdx.x * 256 + tid;
    int px = i / (CHI / 8);
    int c0 = (i % (CHI / 8)) * 8;
    __half2 hi[4], lo[4];
#pragma unroll
    for (int j = 0; j < 4; ++j) {
        int c = c0 + 2 * j;
        float v0 = 0.f, v1 = 0.f;
        if (c < CIN) {
            float2 v = *(const float2*)(in + (size_t)px * CIN + c);
            v0 = fmaxf(v.x * ss[c] + sh[c], 0.f);
            v1 = fmaxf(v.y * ss[c + 1] + sh[c + 1], 0.f);
        }
        __half h0 = __float2half_rn(v0), h1 = __float2half_rn(v1);
        hi[j] = __halves2half2(h0, h1);
        lo[j] = __floats2half2_rn(v0 - __half2float(h0), v1 - __half2float(h1));
    }
    *(uint4*)(out + (size_t)px * (2 * CHI) + c0)       = *(const uint4*)hi;
    *(uint4*)(out + (size_t)px * (2 * CHI) + CHI + c0) = *(const uint4*)lo;
}

// ---------------- weight prep ----------------
__global__ void w16prep(const float* __restrict__ w, __half* __restrict__ o,
                        int NTAP, int OCT, int ICP, int Cout, int Cin) {
    int i = blockIdx.x * 256 + threadIdx.x;
    if (i >= NTAP * OCT * ICP) return;
    int tap = i / (OCT * ICP);
    int r = i - tap * (OCT * ICP);
    int oc = r / ICP, ic = r - oc * ICP;
    float v = (oc < Cout && ic < Cin) ? w[((size_t)oc * Cin + ic) * NTAP + tap] : 0.f;
    o[i] = __float2half_rn(v);
}
__global__ void w16prep_hl(const float* __restrict__ w, __half* __restrict__ o,
                           int NTAP, int OCT, int ICP, int Cout, int Cin) {
    int i = blockIdx.x * 256 + threadIdx.x;
    if (i >= NTAP * OCT * ICP) return;
    int tap = i / (OCT * ICP);
    int r = i - tap * (OCT * ICP);
    int oc = r / ICP, ic = r - oc * ICP;
    float v = (oc < Cout && ic < Cin) ? w[((size_t)oc * Cin + ic) * NTAP + tap] : 0.f;
    __half h = __float2half_rn(v);
    size_t base = ((size_t)tap * OCT + oc) * (2 * ICP);
    o[base + ic] = h;
    o[base + ICP + ic] = __float2half_rn(v - __half2float(h));
}

// ---------------- HMMA implicit-GEMM conv: cp.async ring, optional pairing ---
template<int K, int ICH, int CINP, int OCT, int COUT, int PHASES, bool PAIRED>
__global__ __launch_bounds__(256) void conv_hmma(
    const __half* __restrict__ in, const __half* __restrict__ w16,
    float* __restrict__ out, float* __restrict__ stats)
{
    constexpr int PAD = K / 2;
    constexpr int RWIN = 128 + 2 * PAD;
    constexpr int NS = K * K * PHASES * ICH;
    constexpr int BW = (PHASES == 3 ? 2 : 1) * ICH * 64;
    constexpr int ABYTES = RWIN * 128;
    constexpr int BBYTES = OCT * 128;
    constexpr int BSLOTS = PAIRED ? 6 : 3;
    constexpr int NJ = OCT / 16;
    constexpr int NI2 = NJ / 2;
    constexpr int BLK = K * PHASES;
    constexpr int BPER = (OCT * 8) / 256;

    extern __shared__ __align__(16) char sm[];
    float* sacc = (float*)(sm + 3 * ABYTES + BSLOTS * BBYTES);
    float* qacc = sacc + OCT;

    int tid = threadIdx.x;
    int lane = tid & 31, wrp = tid >> 5;
    int mw = wrp >> 1, nw = wrp & 1;
    int p0 = blockIdx.x * 128;
    int n = p0 >> 16;
    int y = (p0 >> 8) & 255;
    int x0 = p0 & 255;
    uint32_t sbase = smem_u32(sm);

    float acc[2][NJ][4];
#pragma unroll
    for (int mi = 0; mi < 2; ++mi)
#pragma unroll
        for (int nj = 0; nj < NJ; ++nj)
#pragma unroll
            for (int e = 0; e < 4; ++e) acc[mi][nj][e] = 0.f;

    auto decode = [&](int s, int& ky, int& aoff, int& boff, int& kx, int& a_id) {
        int t0 = s / (BLK * ICH);
        int t1 = s - t0 * BLK * ICH;
        int i  = t1 / BLK;
        int u  = t1 - i * BLK;
        int seg = u / K;
        kx = u - seg * K;
        ky = t0;
        aoff = (seg == 2) ? ICH + i : i;
        boff = (seg == 1) ? ICH + i : i;
        a_id = (PHASES == 3) ? ((t0 * ICH + i) * 2 + (seg == 2 ? 1 : 0))
                             : (t0 * ICH + i);
    };

    auto stageA = [&](int ky, int aoff, int slot) {
        uint32_t base = sbase + slot * ABYTES;
        int gy = y + ky - PAD;
        int hh = tid & 1;
        bool rowok = (unsigned)gy < 256u;
        for (int r = tid >> 1; r < RWIN; r += 128) {
            int gx = x0 + r - PAD;
            bool ok = rowok && (unsigned)gx < 256u;
            const __half* src = in + ((size_t)((n * 256 + (ok ? gy : 0)) * 256 + (ok ? gx : 0))) * CINP
                                + aoff * 64 + hh * 32;
            int sz = ok ? 16 : 0;
#pragma unroll
            for (int j = 0; j < 4; ++j) {
                uint32_t bo = (uint32_t)r * 128 + hh * 64 + j * 16;
                cp16z(base + SW128(bo), src + j * 8, sz);
            }
        }
    };
    auto stageB = [&](int tap, int boff, int slot) {
        uint32_t base = sbase + 3 * ABYTES + slot * BBYTES;
#pragma unroll
        for (int j = 0; j < BPER; ++j) {
            int idx = tid * BPER + j;
            int row = idx >> 3, q = idx & 7;
            const __half* src = w16 + ((size_t)tap * OCT + row) * BW + boff * 64 + q * 8;
            uint32_t bo = (uint32_t)row * 128 + q * 16;
            cp16(base + SW128(bo), src);
        }
    };
    auto consume = [&](int s_, int kx_, int aid_) {
        uint32_t abase = sbase + (aid_ % 3) * ABYTES;
        uint32_t bbase = sbase + 3 * ABYTES + (s_ % BSLOTS) * BBYTES;
#pragma unroll
        for (int kk = 0; kk < 4; ++kk) {
            uint32_t bo = kk * 32 + ((lane >> 4) << 4);
            uint32_t afr[2][4];
#pragma unroll
            for (int mi = 0; mi < 2; ++mi) {
                uint32_t row = mw * 32 + mi * 16 + (lane & 15) + kx_;
                ldsm_x4(afr[mi][0], afr[mi][1], afr[mi][2], afr[mi][3],
                        abase + SW128(row * 128 + bo));
            }
#pragma unroll
            for (int ni = 0; ni < NI2; ++ni) {
                uint32_t row = nw * (OCT / 2) + ni * 16 + (lane & 15);
                uint32_t b0, b1, b2, b3;
                ldsm_x4(b0, b1, b2, b3, bbase + SW128(row * 128 + bo));
#pragma unroll
                for (int mi = 0; mi < 2; ++mi) {
                    mma16816(acc[mi][ni * 2],     afr[mi], b0, b2);
                    mma16816(acc[mi][ni * 2 + 1], afr[mi], b1, b3);
                }
            }
        }
    };

    if (PAIRED) {
        int aid_last;
        {
            int ky, ao, bo, kx, ai;
            decode(0, ky, ao, bo, kx, ai);
            stageA(ky, ao, ai % 3);
            stageB(ky * K + kx, bo, 0);
            aid_last = ai;
            if (NS > 1) {
                decode(1, ky, ao, bo, kx, ai);
                stageB(ky * K + kx, bo, 1);
                if (ai != aid_last) { stageA(ky, ao, ai % 3); aid_last = ai; }
            }
            CP_COMMIT();
        }
        for (int s0 = 0; s0 < NS; s0 += 2) {
            if (s0 + 2 < NS) {
                int ky, ao, bo, kx, ai;
                decode(s0 + 2, ky, ao, bo, kx, ai);
                stageB(ky * K + kx, bo, (s0 + 2) % BSLOTS);
                if (ai != aid_last) { stageA(ky, ao, ai % 3); aid_last = ai; }
                if (s0 + 3 < NS) {
                    decode(s0 + 3, ky, ao, bo, kx, ai);
                    stageB(ky * K + kx, bo, (s0 + 3) % BSLOTS);
                    if (ai != aid_last) { stageA(ky, ao, ai % 3); aid_last = ai; }
                }
                CP_COMMIT();
                CP_WAIT(1);
            } else {
                CP_WAIT(0);
            }
            __syncthreads();
            {
                int ky, ao, bo, kx, ai;
                decode(s0, ky, ao, bo, kx, ai);
                consume(s0, kx, ai);
            }
            if (s0 + 1 < NS) {
                int ky, ao, bo, kx, ai;
                decode(s0 + 1, ky, ao, bo, kx, ai);
                consume(s0 + 1, kx, ai);
            }
        }
    } else {
        {
            int ky, ao, bo, kx, ai;
            decode(0, ky, ao, bo, kx, ai);
            stageA(ky, ao, ai % 3);
            stageB(ky * K + kx, bo, 0);
            CP_COMMIT();
        }
        int kxc, aic;
        { int ky, ao, bo; decode(0, ky, ao, bo, kxc, aic); }
        for (int s = 0; s < NS; ++s) {
            if (s + 1 < NS) {
                int ky2, ao2, bo2, kx2, ai2;
                decode(s + 1, ky2, ao2, bo2, kx2, ai2);
                stageB(ky2 * K + kx2, bo2, (s + 1) % BSLOTS);
                if (ai2 != aic) stageA(ky2, ao2, ai2 % 3);
                CP_COMMIT();
                CP_WAIT(1);
                __syncthreads();
                consume(s, kxc, aic);
                kxc = kx2; aic = ai2;
            } else {
                CP_WAIT(0);
                __syncthreads();
                consume(s, kxc, aic);
            }
        }
    }
    __syncthreads();

    if (tid < OCT) { sacc[tid] = 0.f; qacc[tid] = 0.f; }
    __syncthreads();

#pragma unroll
    for (int nj = 0; nj < NJ; ++nj) {
        int col = nw * (OCT / 2) + nj * 8 + (lane & 3) * 2;
        if (col < COUT) {
            float s0 = 0.f, s1 = 0.f, q0 = 0.f, q1 = 0.f;
#pragma unroll
            for (int mi = 0; mi < 2; ++mi) {
                int row = mw * 32 + mi * 16 + (lane >> 2);
                float d0 = acc[mi][nj][0], d1 = acc[mi][nj][1];
                float d2 = acc[mi][nj][2], d3 = acc[mi][nj][3];
                *(float2*)(out + (size_t)(p0 + row) * COUT + col)     = make_float2(d0, d1);
                *(float2*)(out + (size_t)(p0 + row + 8) * COUT + col) = make_float2(d2, d3);
                s0 += d0 + d2; s1 += d1 + d3;
                q0 += d0 * d0 + d2 * d2; q1 += d1 * d1 + d3 * d3;
            }
            atomicAdd(&sacc[col], s0);     atomicAdd(&sacc[col + 1], s1);
            atomicAdd(&qacc[col], q0);     atomicAdd(&qacc[col + 1], q1);
        }
    }
    __syncthreads();
    if (tid < OCT && tid < COUT) {
        atomicAdd(&stats[tid], sacc[tid]);
        atomicAdd(&stats[128 + tid], qacc[tid]);
    }
}

// ---------------- obj2 1x1 (48->20), in-kernel bnfin(bn4)+relu ---------------
__global__ __launch_bounds__(256) void obj2_kernel(
    const float* __restrict__ in, const float* __restrict__ w,
    const float* __restrict__ b,
    const float* __restrict__ g4, const float* __restrict__ b4,
    const float* __restrict__ stats, float* __restrict__ out)
{
    __shared__ float wst[48 * 20];
    __shared__ float bs[20];
    __shared__ float ss[48], sh[48];
    int tid = threadIdx.x;
    if (tid < 48) {
        float inv = 1.f / (float)NPIX;
        float mu  = stats[tid] * inv;
        float var = stats[128 + tid] * inv - mu * mu;
        float sc  = g4[tid] * rsqrtf(var + 1e-5f);
        ss[tid] = sc;
        sh[tid] = b4[tid] - mu * sc;
    }
    for (int i = tid; i < 48 * 20; i += 256) {
        int o = i / 48, ic = i - o * 48;
        wst[ic * 20 + o] = w[o * 48 + ic];
    }
    if (tid < 20) bs[tid] = b[tid];
    __syncthreads();

    int p = blockIdx.x * 256 + tid;
    int n = p >> 16, pix = p & 65535;
    const float* ip = in + (size_t)p * 48;
    u64 accp[10];
#pragma unroll
    for (int o = 0; o < 10; ++o) accp[o] = pack2f(bs[2 * o], bs[2 * o + 1]);
#pragma unroll
    for (int ic = 0; ic < 48; ++ic) {
        float v = fmaxf(ip[ic] * ss[ic] + sh[ic], 0.f);
        u64 vb = bcast2(v);
#pragma unroll
        for (int o = 0; o < 10; ++o) {
            u64 wp = *(const u64*)&wst[ic * 20 + 2 * o];
            accp[o] = ffma2(wp, vb, accp[o]);
        }
    }
#pragma unroll
    for (int o = 0; o < 10; ++o) {
        float2 f = unpk(accp[o]);
        out[((size_t)(n * NOBJ + 2 * o)     << 16) + pix] = f.x;
        out[((size_t)(n * NOBJ + 2 * o + 1) << 16) + pix] = f.y;
    }
}

// ---------------- launch ----------------
extern "C" void kernel_launch(void* const* d_in, const int* in_sizes, int n_in,
                              void* d_out, int out_size)
{
    const float* feats  = (const float*)d_in[0];
    const int*   masks  = (const int*)  d_in[1];
    const float* w_ih   = (const float*)d_in[2];
    const float* w_hh   = (const float*)d_in[3];
    const float* b_ih   = (const float*)d_in[4];
    const float* b_hh   = (const float*)d_in[5];
    const float* conv1w = (const float*)d_in[6];
    const float* bn1g   = (const float*)d_in[7];
    const float* bn1b   = (const float*)d_in[8];
    const float* conv2w = (const float*)d_in[9];
    const float* bn2g   = (const float*)d_in[10];
    const float* bn2b   = (const float*)d_in[11];
    const float* conv3w = (const float*)d_in[12];
    const float* bn3g   = (const float*)d_in[13];
    const float* bn3b   = (const float*)d_in[14];
    const float* obj1w  = (const float*)d_in[15];
    const float* bn4g   = (const float*)d_in[16];
    const float* bn4b   = (const float*)d_in[17];
    const float* obj2w  = (const float*)d_in[18];
    const float* obj2b  = (const float*)d_in[19];
    float* out = (float*)d_out;

    void *pany, *pstats, *pbA, *pbB, *phA, *phB, *pf16, *pact, *pw16, *pw16b, *pw16g;
    cudaGetSymbolAddress(&pany, g_any);
    cudaGetSymbolAddress(&pstats, g_stats);
    cudaGetSymbolAddress(&pbA, g_bufA);
    cudaGetSymbolAddress(&pbB, g_bufB);
    cudaGetSymbolAddress(&phA, g_hA);
    cudaGetSymbolAddress(&phB, g_hB);
    cudaGetSymbolAddress(&pf16, g_f16);
    cudaGetSymbolAddress(&pact, g_act16);
    cudaGetSymbolAddress(&pw16, g_w16);
    cudaGetSymbolAddress(&pw16b, g_w16b);
    cudaGetSymbolAddress(&pw16g, g_w16g);
    float* bA = (float*)pbA;
    float* bB = (float*)pbB;
    __half* hA = (__half*)phA;
    __half* hB = (__half*)phB;
    __half* f16 = (__half*)pf16;
    __half* act = (__half*)pact;
    __half* w16 = (__half*)pw16;
    __half* w16b = (__half*)pw16b;
    __half* w16g = (__half*)pw16g;
    float* stats = (float*)pstats;

    auto* g0 = gru_hmma<true>;
    auto* g1 = gru_hmma<false>;
    auto* c1 = conv_hmma<7, 2, 128, 128, 128, 1, false>;
    auto* c2 = conv_hmma<3, 2, 256, 64, 64, 3, true>;
    auto* c3 = conv_hmma<3, 1, 128, 64, 48, 3, true>;
    const int SM1 = 3 * (134 * 128) + 3 * 16384 + 128 * 8;   // 101632
    const int SM2 = 3 * (130 * 128) + 6 * 8192 + 64 * 8;     // 99584
    cudaFuncSetAttribute(g0, cudaFuncAttributeMaxDynamicSharedMemorySize, GRU_SMEM);
    cudaFuncSetAttribute(g1, cudaFuncAttributeMaxDynamicSharedMemorySize, GRU_SMEM);
    cudaFuncSetAttribute(c1, cudaFuncAttributeMaxDynamicSharedMemorySize, SM1);
    cudaFuncSetAttribute(c2, cudaFuncAttributeMaxDynamicSharedMemorySize, SM2);
    cudaFuncSetAttribute(c3, cudaFuncAttributeMaxDynamicSharedMemorySize, SM2);

    // launch order: memset, memset, w16gru_prep, f16feat, g0, g1 (#6 profiled)
    cudaMemsetAsync(pany, 0, sizeof(g_any));
    cudaMemsetAsync(pstats, 0, sizeof(g_stats));
    w16gru_prep<<<384, 256>>>(w_ih, w_hh, w16g);
    f16feat<<<16384, 256>>>(feats, f16);

    dim3 ggrid(1024, 4);
    g0<<<ggrid, 256, GRU_SMEM>>>(f16, masks, w16g, b_ih, b_hh, hA, hA, 0);
    g1<<<ggrid, 256, GRU_SMEM>>>(f16, masks, w16g, b_ih, b_hh, hA, hB, 1);
    g1<<<ggrid, 256, GRU_SMEM>>>(f16, masks, w16g, b_ih, b_hh, hB, hA, 2);
    g1<<<ggrid, 256, GRU_SMEM>>>(f16, masks, w16g, b_ih, b_hh, hA, hB, 3);

    // mask outputs + conv weight preps
    any_kernel<<<2048, 256>>>(masks);
    obs_kernel<<<512, 256>>>(masks, out + (size_t)NB * NOBJ * HW);
    w16prep<<<3136, 256>>>(conv1w, w16, 49, 128, 128, 128, 128);
    w16prep_hl<<<288, 256>>>(conv2w, w16b,          9, 64, 128, 64, 128);
    w16prep_hl<<<144, 256>>>(conv3w, w16b + 147456, 9, 64,  64, 48,  64);
    w16prep_hl<<<144, 256>>>(obj1w,  w16b + 221184, 9, 64,  64, 48,  48);

    // conv1 7x7 128->128
    c1<<<1024, 256, SM1>>>(hB, w16, bB, stats);

    // conv2 3x3 128->64 (hi/lo, paired)
    bnrelu_hl<128, 128><<<8192, 256>>>(bB, act, bn1g, bn1b, stats);
    c2<<<1024, 256, SM2>>>(act, w16b, bA, stats + 256);

    // conv3 3x3 64->48 (hi/lo, paired)
    bnrelu_hl<64, 64><<<4096, 256>>>(bA, act, bn2g, bn2b, stats + 256);
    c3<<<1024, 256, SM2>>>(act, w16b + 147456, bB, stats + 512);

    // obj1 3x3 48->48 (hi/lo, paired)
    bnrelu_hl<48, 64><<<4096, 256>>>(bB, act, bn3g, bn3b, stats + 512);
    c3<<<1024, 256, SM2>>>(act, w16b + 221184, bA, stats + 768);

    // obj2 1x1 48->20 + bias (in-kernel bn4+relu)
    obj2_kernel<<<512, 256>>>(bA, obj2w, obj2b, bn4g, bn4b, stats + 768, out);
}

// round 16
// speedup vs baseline: 1.0285x; 1.0285x over previous
#include <cuda_runtime.h>
#include <cuda_fp16.h>
#include <cstdint>

#define EGO   64
#define MEM   128
#define NOBJ  20
#define HW    65536     // 256*256
#define NPIX  131072    // 2 * HW
#define NB    2
#define TT    4

typedef unsigned long long u64;

// ---------------- packed f32x2 helpers ----------------
__device__ __forceinline__ u64 bcast2(float x) {
    u64 r; asm("mov.b64 %0, {%1, %1};" : "=l"(r) : "f"(x)); return r;
}
__device__ __forceinline__ u64 pack2f(float x, float y) {
    u64 r; asm("mov.b64 %0, {%1, %2};" : "=l"(r) : "f"(x), "f"(y)); return r;
}
__device__ __forceinline__ u64 ffma2(u64 a, u64 b, u64 c) {
    u64 d; asm("fma.rn.f32x2 %0, %1, %2, %3;" : "=l"(d) : "l"(a), "l"(b), "l"(c)); return d;
}
__device__ __forceinline__ float2 unpk(u64 a) {
    float2 f; asm("mov.b64 {%0, %1}, %2;" : "=f"(f.x), "=f"(f.y) : "l"(a)); return f;
}

// ---------------- fast transcendentals ----------------
__device__ __forceinline__ float fast_sigmoid(float x) {
    float e; asm("ex2.approx.f32 %0, %1;" : "=f"(e) : "f"(-1.4426950408889634f * x));
    float r; asm("rcp.approx.f32 %0, %1;" : "=f"(r) : "f"(1.f + e));
    return r;
}
__device__ __forceinline__ float fast_tanh(float x) {
    float e; asm("ex2.approx.f32 %0, %1;" : "=f"(e) : "f"(2.8853900817779268f * x));
    float r; asm("rcp.approx.f32 %0, %1;" : "=f"(r) : "f"(1.f + e));
    return 1.f - 2.f * r;
}

// ---------------- smem / swizzle / mma / cp.async helpers ----------------
__device__ __forceinline__ uint32_t smem_u32(const void* p) {
    uint32_t a; asm("{ .reg .u64 t; cvta.to.shared.u64 t, %1; cvt.u32.u64 %0, t; }" : "=r"(a) : "l"(p));
    return a;
}
#define SW128(o) ((o) ^ (((o) >> 3) & 0x70))

__device__ __forceinline__ void ldsm_x4(uint32_t& r0, uint32_t& r1, uint32_t& r2, uint32_t& r3,
                                        uint32_t addr) {
    asm volatile("ldmatrix.sync.aligned.m8n8.x4.shared.b16 {%0,%1,%2,%3}, [%4];"
                 : "=r"(r0), "=r"(r1), "=r"(r2), "=r"(r3) : "r"(addr));
}
__device__ __forceinline__ void mma16816(float* c, const uint32_t* a, uint32_t b0, uint32_t b1) {
    asm volatile(
        "mma.sync.aligned.m16n8k16.row.col.f32.f16.f16.f32 "
        "{%0,%1,%2,%3}, {%4,%5,%6,%7}, {%8,%9}, {%0,%1,%2,%3};"
        : "+f"(c[0]), "+f"(c[1]), "+f"(c[2]), "+f"(c[3])
        : "r"(a[0]), "r"(a[1]), "r"(a[2]), "r"(a[3]), "r"(b0), "r"(b1));
}
__device__ __forceinline__ void cp16(uint32_t dst, const void* src) {
    asm volatile("cp.async.cg.shared.global [%0], [%1], 16;" :: "r"(dst), "l"(src));
}
__device__ __forceinline__ void cp16z(uint32_t dst, const void* src, int sz) {
    asm volatile("cp.async.cg.shared.global [%0], [%1], 16, %2;" :: "r"(dst), "l"(src), "r"(sz));
}
#define CP_COMMIT() asm volatile("cp.async.commit_group;" ::: "memory")
#define CP_WAIT(n)  asm volatile("cp.async.wait_group %0;" :: "n"(n) : "memory")

// ---------------- static scratch ----------------
__device__ __half g_hA[(size_t)NPIX * 128];
__device__ __half g_hB[(size_t)NPIX * 128];
__device__ __half g_f16[(size_t)NPIX * TT * 64];  // fp16 features
__device__ __half g_act16[(size_t)NPIX * 256];
__device__ float  g_bufA[(size_t)NPIX * 128];
__device__ float  g_bufB[(size_t)NPIX * 128];
__device__ __half g_w16[49 * 128 * 128];         // conv1
__device__ __half g_w16b[300000];                // conv2 @0, conv3 @147456, obj1 @221184
__device__ __half g_w16g[4 * 3 * 128 * 64];      // GRU
__device__ int    g_any[8];
__device__ float  g_stats[1024];                 // 4 segments of 256

// ---------------- any / observed ----------------
__global__ void any_kernel(const int* __restrict__ masks) {
    int idx = blockIdx.x * blockDim.x + threadIdx.x;
    int v = masks[idx];
    unsigned b = __ballot_sync(0xffffffffu, v > 0);
    if ((threadIdx.x & 31) == 0 && b)
        atomicOr(&g_any[idx >> 16], 1);
}
__global__ void obs_kernel(const int* __restrict__ masks, float* __restrict__ outobs) {
    int idx = blockIdx.x * blockDim.x + threadIdx.x;
    int n = idx >> 16, pix = idx & 65535;
    int s = 0;
#pragma unroll
    for (int t = 0; t < TT; ++t)
        s += masks[((n * TT + t) << 16) + pix] * g_any[n * TT + t];
    outobs[idx] = (float)s;
}

// ---------------- feats fp32 -> fp16 ----------------
__global__ void f16feat(const float* __restrict__ in, __half* __restrict__ out) {
    size_t i = ((size_t)blockIdx.x * 256 + threadIdx.x) * 8;
    float4 a = *(const float4*)(in + i);
    float4 b = *(const float4*)(in + i + 4);
    __half2 h[4] = { __floats2half2_rn(a.x, a.y), __floats2half2_rn(a.z, a.w),
                     __floats2half2_rn(b.x, b.y), __floats2half2_rn(b.z, b.w) };
    *(uint4*)(out + i) = *(const uint4*)h;
}

// ---------------- GRU weight prep (gate-grouped columns) ----------------
__global__ void w16gru_prep(const float* __restrict__ wih, const float* __restrict__ whh,
                            __half* __restrict__ o) {
    int i = blockIdx.x * 256 + threadIdx.x;
    if (i >= 4 * 3 * 128 * 64) return;
    int bb = i / 24576; int r = i - bb * 24576;
    int c  = r / 8192;  int r2 = r - c * 8192;
    int row = r2 >> 6;  int kk = r2 & 63;
    int g4 = row >> 5, ul = row & 31;
    int gu = bb * 32 + ul;
    float v = 0.f;
    if (g4 == 0)      v = (c == 0) ? wih[(      gu) * 64 + kk] : whh[(      gu) * 128 + (c - 1) * 64 + kk];
    else if (g4 == 1) v = (c == 0) ? wih[(128 + gu) * 64 + kk] : whh[(128 + gu) * 128 + (c - 1) * 64 + kk];
    else if (g4 == 2) v = (c == 0) ? wih[(256 + gu) * 64 + kk] : 0.f;
    else              v = (c == 0) ? 0.f : whh[(256 + gu) * 128 + (c - 1) * 64 + kk];
    o[i] = __float2half_rn(v);
}

// ---------------- GRU step via HMMA (cp.async pre-stage, zero-sync) ----------
#define GRU_SMEM (98304 + 768 + 32 + 512 + 512)
#define GSTR 132

template<bool FIRST>
__global__ __launch_bounds__(256, 2) void gru_hmma(
    const __half* __restrict__ f16, const int* __restrict__ masks,
    const __half* __restrict__ w16g,
    const float* __restrict__ b_ih, const float* __restrict__ b_hh,
    const __half* __restrict__ hin, __half* __restrict__ hout, int t)
{
    extern __shared__ char sm[];
    float* gbuf = (float*)sm;
    float* sbias = (float*)(sm + 98304);
    int* wcnt  = (int*)(sm + 98304 + 768);
    int* cnts  = (int*)(sm + 98304 + 768 + 16);
    int* clist = (int*)(sm + 98304 + 768 + 32);
    int* ulist = (int*)(sm + 98304 + 768 + 32 + 512);

    int tid = threadIdx.x;
    int lane = tid & 31, wrp = tid >> 5;
    int mw = wrp >> 1, nw = wrp & 1;
    int p0 = blockIdx.x * 128;
    int bb = blockIdx.y;
    int ub = bb * 32;
    int n = p0 >> 16, pix0 = p0 & 65535;
    uint32_t sbase = smem_u32(sm);

    const int* mrow = masks + ((size_t)(n * TT + t) << 16) + pix0;

    const int CH = FIRST ? 1 : 3;
    int px = tid >> 1, sg = tid & 1;

    // ---- stage everything via cp.async ----
    {
        int sr = tid >> 1, h2 = tid & 1;
#pragma unroll
        for (int c = 0; c < 3; ++c) {
            if (c >= CH) break;
            const __half* src = w16g + ((size_t)((bb * 3 + c) * 128 + sr)) * 64 + h2 * 32;
            uint32_t base = sbase + 49152 + c * 16384;
#pragma unroll
            for (int j = 0; j < 4; ++j) {
                uint32_t bo = (uint32_t)sr * 128 + h2 * 64 + j * 16;
                cp16(base + SW128(bo), src + j * 8);
            }
        }
    }
    {
        const __half* src = f16 + ((size_t)(n * TT + t) * HW + pix0 + px) * 64 + sg * 32;
#pragma unroll
        for (int j = 0; j < 4; ++j) {
            uint32_t bo = (uint32_t)px * 128 + sg * 64 + j * 16;
            cp16(sbase + SW128(bo), src + j * 8);
        }
    }
    if (!FIRST) {
#pragma unroll
        for (int c = 1; c < 3; ++c) {
            const __half* src = hin + ((size_t)(p0 + px)) * 128 + (c - 1) * 64 + sg * 32;
            uint32_t base = sbase + c * 16384;
#pragma unroll
            for (int j = 0; j < 4; ++j) {
                uint32_t bo = (uint32_t)px * 128 + sg * 64 + j * 16;
                cp16(base + SW128(bo), src + j * 8);
            }
        }
    }
    CP_COMMIT();

    int mv = 0; int posm = 0;
    if (tid < 128) {
        mv = mrow[tid] > 0;
        unsigned bal = __ballot_sync(0xffffffffu, mv);
        posm = __popc(bal & ((1u << lane) - 1));
        if (lane == 0) wcnt[tid >> 5] = __popc(bal);
    }
    if (tid < 96) {
        int g = tid >> 5, u = tid & 31;
        sbias[tid] = b_ih[g * 128 + ub + u];
    } else if (tid < 192) {
        int t2 = tid - 96;
        int g = t2 >> 5, u = t2 & 31;
        sbias[tid] = b_hh[g * 128 + ub + u];
    }

    CP_WAIT(0);
    __syncthreads();
    if (tid < 128) {
        int w = tid >> 5;
        int off = 0;
#pragma unroll
        for (int j = 0; j < 4; ++j) if (j < w) off += wcnt[j];
        if (mv) clist[off + posm] = tid;
        else    ulist[32 * w - off + lane - posm] = tid;
        if (tid == 0) cnts[0] = wcnt[0] + wcnt[1] + wcnt[2] + wcnt[3];
    }

    float acc[2][8][4];
#pragma unroll
    for (int mi = 0; mi < 2; ++mi)
#pragma unroll
        for (int nj = 0; nj < 8; ++nj)
#pragma unroll
            for (int e = 0; e < 4; ++e) acc[mi][nj][e] = 0.f;

#pragma unroll
    for (int c = 0; c < 3; ++c) {
        if (c >= CH) break;
        uint32_t abase = sbase + c * 16384;
        uint32_t bbase = sbase + 49152 + c * 16384;
#pragma unroll
        for (int kk = 0; kk < 4; ++kk) {
            uint32_t bo = kk * 32 + ((lane >> 4) << 4);
            uint32_t afr[2][4];
#pragma unroll
            for (int mi = 0; mi < 2; ++mi) {
                uint32_t row = mw * 32 + mi * 16 + (lane & 15);
                ldsm_x4(afr[mi][0], afr[mi][1], afr[mi][2], afr[mi][3],
                        abase + SW128(row * 128 + bo));
            }
            auto dob = [&](int ni) {
                uint32_t row = nw * 64 + ni * 16 + (lane & 15);
                uint32_t b0, b1, b2, b3;
                ldsm_x4(b0, b1, b2, b3, bbase + SW128(row * 128 + bo));
#pragma unroll
                for (int mi = 0; mi < 2; ++mi) {
                    mma16816(acc[mi][ni * 2],     afr[mi], b0, b2);
                    mma16816(acc[mi][ni * 2 + 1], afr[mi], b1, b3);
                }
            };
            if (nw == 0) { dob(0); dob(1); dob(2); dob(3); }
            else if (c == 0) { dob(0); dob(1); }
            else { dob(2); dob(3); }
        }
    }
    __syncthreads();

#pragma unroll
    for (int mi = 0; mi < 2; ++mi)
#pragma unroll
        for (int nj = 0; nj < 8; ++nj) {
            int row = mw * 32 + mi * 16 + (lane >> 2);
            int col = nw * 64 + nj * 8 + (lane & 3) * 2;
            *(float2*)&gbuf[row * GSTR + col]       = make_float2(acc[mi][nj][0], acc[mi][nj][1]);
            *(float2*)&gbuf[(row + 8) * GSTR + col] = make_float2(acc[mi][nj][2], acc[mi][nj][3]);
        }
    __syncthreads();

    int cnt = cnts[0];
    for (int i = tid; i < 2 * cnt; i += 256) {
        int pxl = clist[i >> 1];
        int half = i & 1;
        __half hold[16];
        if (!FIRST) {
            const __half* hp = hin + ((size_t)(p0 + pxl)) * 128 + ub + half * 16;
            *(uint4*)&hold[0] = *(const uint4*)hp;
            *(uint4*)&hold[8] = *(const uint4*)(hp + 8);
        }
        __half hnew[16];
#pragma unroll
        for (int ug = 0; ug < 4; ++ug) {
            int cb = half * 16 + ug * 4;
            float4 rr = *(float4*)&gbuf[pxl * GSTR + cb];
            float4 zz = *(float4*)&gbuf[pxl * GSTR + 32 + cb];
            float4 xx = *(float4*)&gbuf[pxl * GSTR + 64 + cb];
            float4 hh4 = *(float4*)&gbuf[pxl * GSTR + 96 + cb];
            float rv[4] = { rr.x, rr.y, rr.z, rr.w };
            float zv[4] = { zz.x, zz.y, zz.z, zz.w };
            float xv[4] = { xx.x, xx.y, xx.z, xx.w };
            float hv4[4] = { hh4.x, hh4.y, hh4.z, hh4.w };
#pragma unroll
            for (int e = 0; e < 4; ++e) {
                int ul = cb + e;
                float r = fast_sigmoid(rv[e] + sbias[ul] + sbias[96 + ul]);
                float z = fast_sigmoid(zv[e] + sbias[32 + ul] + sbias[128 + ul]);
                float nv = fast_tanh(xv[e] + sbias[64 + ul] + r * (hv4[e] + sbias[160 + ul]));
                float ho = FIRST ? 0.f : __half2float(hold[ug * 4 + e]);
                float hv = nv + z * (ho - nv);
                hnew[ug * 4 + e] = __float2half_rn(hv);
            }
        }
        __half* op = hout + ((size_t)(p0 + pxl)) * 128 + ub + half * 16;
        *(uint4*)op       = *(const uint4*)&hnew[0];
        *(uint4*)(op + 8) = *(const uint4*)&hnew[8];
    }
    int un = 128 - cnt;
    for (int i = tid; i < 2 * un; i += 256) {
        int pxl = ulist[i >> 1];
        int half = i & 1;
        __half* op = hout + ((size_t)(p0 + pxl)) * 128 + ub + half * 16;
        if (FIRST) {
            uint4 z = make_uint4(0, 0, 0, 0);
            *(uint4*)op = z; *(uint4*)(op + 8) = z;
        } else {
            const __half* hp = hin + ((size_t)(p0 + pxl)) * 128 + ub + half * 16;
            *(uint4*)op       = *(const uint4*)hp;
            *(uint4*)(op + 8) = *(const uint4*)(hp + 8);
        }
    }
}

// ---------------- bn+relu (in-kernel bnfin) f32 -> hi/lo fp16 ----------------
template<int CIN, int CHI>
__global__ void bnrelu_hl(const float* __restrict__ in, __half* __restrict__ out,
                          const float* __restrict__ g, const float* __restrict__ b,
                          const float* __restrict__ stats) {
    __shared__ float ss[CIN], sh[CIN];
    int tid = threadIdx.x;
    if (tid < CIN) {
        float inv = 1.f / (float)NPIX;
        float mu  = stats[tid] * inv;
        float var = stats[128 + tid] * inv - mu * mu;
        float sc  = g[tid] * rsqrtf(var + 1e-5f);
        ss[tid] = sc;
        sh[tid] = b[tid] - mu * sc;
    }
    __syncthreads();

    int i = blockIdx.x * 256 + tid;
    int px = i / (CHI / 8);
    int c0 = (i % (CHI / 8)) * 8;
    __half2 hi[4], lo[4];
#pragma unroll
    for (int j = 0; j < 4; ++j) {
        int c = c0 + 2 * j;
        float v0 = 0.f, v1 = 0.f;
        if (c < CIN) {
            float2 v = *(const float2*)(in + (size_t)px * CIN + c);
            v0 = fmaxf(v.x * ss[c] + sh[c], 0.f);
            v1 = fmaxf(v.y * ss[c + 1] + sh[c + 1], 0.f);
        }
        __half h0 = __float2half_rn(v0), h1 = __float2half_rn(v1);
        hi[j] = __halves2half2(h0, h1);
        lo[j] = __floats2half2_rn(v0 - __half2float(h0), v1 - __half2float(h1));
    }
    *(uint4*)(out + (size_t)px * (2 * CHI) + c0)       = *(const uint4*)hi;
    *(uint4*)(out + (size_t)px * (2 * CHI) + CHI + c0) = *(const uint4*)lo;
}

// ---------------- weight prep ----------------
__global__ void w16prep(const float* __restrict__ w, __half* __restrict__ o,
                        int NTAP, int OCT, int ICP, int Cout, int Cin) {
    int i = blockIdx.x * 256 + threadIdx.x;
    if (i >= NTAP * OCT * ICP) return;
    int tap = i / (OCT * ICP);
    int r = i - tap * (OCT * ICP);
    int oc = r / ICP, ic = r - oc * ICP;
    float v = (oc < Cout && ic < Cin) ? w[((size_t)oc * Cin + ic) * NTAP + tap] : 0.f;
    o[i] = __float2half_rn(v);
}
__global__ void w16prep_hl(const float* __restrict__ w, __half* __restrict__ o,
                           int NTAP, int OCT, int ICP, int Cout, int Cin) {
    int i = blockIdx.x * 256 + threadIdx.x;
    if (i >= NTAP * OCT * ICP) return;
    int tap = i / (OCT * ICP);
    int r = i - tap * (OCT * ICP);
    int oc = r / ICP, ic = r - oc * ICP;
    float v = (oc < Cout && ic < Cin) ? w[((size_t)oc * Cin + ic) * NTAP + tap] : 0.f;
    __half h = __float2half_rn(v);
    size_t base = ((size_t)tap * OCT + oc) * (2 * ICP);
    o[base + ic] = h;
    o[base + ICP + ic] = __float2half_rn(v - __half2float(h));
}

// ---------------- HMMA implicit-GEMM conv: cp.async, 3-slot ring (R13) -------
template<int K, int ICH, int CINP, int OCT, int COUT, int PHASES>
__global__ __launch_bounds__(256) void conv_hmma(
    const __half* __restrict__ in, const __half* __restrict__ w16,
    float* __restrict__ out, float* __restrict__ stats)
{
    constexpr int PAD = K / 2;
    constexpr int RWIN = 128 + 2 * PAD;
    constexpr int NS = K * K * PHASES * ICH;
    constexpr int BW = (PHASES == 3 ? 2 : 1) * ICH * 64;
    constexpr int ABYTES = RWIN * 128;
    constexpr int BBYTES = OCT * 128;
    constexpr int NJ = OCT / 16;
    constexpr int NI2 = NJ / 2;
    constexpr int BLK = K * PHASES;
    constexpr int BPER = (OCT * 8) / 256;

    extern __shared__ __align__(16) char sm[];
    float* sacc = (float*)(sm + 3 * ABYTES + 3 * BBYTES);
    float* qacc = sacc + OCT;

    int tid = threadIdx.x;
    int lane = tid & 31, wrp = tid >> 5;
    int mw = wrp >> 1, nw = wrp & 1;
    int p0 = blockIdx.x * 128;
    int n = p0 >> 16;
    int y = (p0 >> 8) & 255;
    int x0 = p0 & 255;
    uint32_t sbase = smem_u32(sm);

    float acc[2][NJ][4];
#pragma unroll
    for (int mi = 0; mi < 2; ++mi)
#pragma unroll
        for (int nj = 0; nj < NJ; ++nj)
#pragma unroll
            for (int e = 0; e < 4; ++e) acc[mi][nj][e] = 0.f;

    auto decode = [&](int s, int& ky, int& aoff, int& boff, int& kx, int& a_id) {
        int t0 = s / (BLK * ICH);
        int t1 = s - t0 * BLK * ICH;
        int i  = t1 / BLK;
        int u  = t1 - i * BLK;
        int seg = u / K;
        kx = u - seg * K;
        ky = t0;
        aoff = (seg == 2) ? ICH + i : i;
        boff = (seg == 1) ? ICH + i : i;
        a_id = (PHASES == 3) ? ((t0 * ICH + i) * 2 + (seg == 2 ? 1 : 0))
                             : (t0 * ICH + i);
    };

    auto stageA = [&](int ky, int aoff, int slot) {
        uint32_t base = sbase + slot * ABYTES;
        int gy = y + ky - PAD;
        int hh = tid & 1;
        bool rowok = (unsigned)gy < 256u;
        for (int r = tid >> 1; r < RWIN; r += 128) {
            int gx = x0 + r - PAD;
            bool ok = rowok && (unsigned)gx < 256u;
            const __half* src = in + ((size_t)((n * 256 + (ok ? gy : 0)) * 256 + (ok ? gx : 0))) * CINP
                                + aoff * 64 + hh * 32;
            int sz = ok ? 16 : 0;
#pragma unroll
            for (int j = 0; j < 4; ++j) {
                uint32_t bo = (uint32_t)r * 128 + hh * 64 + j * 16;
                cp16z(base + SW128(bo), src + j * 8, sz);
            }
        }
    };
    auto stageB = [&](int tap, int boff, int slot) {
        uint32_t base = sbase + 3 * ABYTES + slot * BBYTES;
#pragma unroll
        for (int j = 0; j < BPER; ++j) {
            int idx = tid * BPER + j;
            int row = idx >> 3, q = idx & 7;
            const __half* src = w16 + ((size_t)tap * OCT + row) * BW + boff * 64 + q * 8;
            uint32_t bo = (uint32_t)row * 128 + q * 16;
            cp16(base + SW128(bo), src);
        }
    };
    auto consume = [&](int s_, int kx_, int aid_) {
        uint32_t abase = sbase + (aid_ % 3) * ABYTES;
        uint32_t bbase = sbase + 3 * ABYTES + (s_ % 3) * BBYTES;
#pragma unroll
        for (int kk = 0; kk < 4; ++kk) {
            uint32_t bo = kk * 32 + ((lane >> 4) << 4);
            uint32_t afr[2][4];
#pragma unroll
            for (int mi = 0; mi < 2; ++mi) {
                uint32_t row = mw * 32 + mi * 16 + (lane & 15) + kx_;
                ldsm_x4(afr[mi][0], afr[mi][1], afr[mi][2], afr[mi][3],
                        abase + SW128(row * 128 + bo));
            }
#pragma unroll
            for (int ni = 0; ni < NI2; ++ni) {
                uint32_t row = nw * (OCT / 2) + ni * 16 + (lane & 15);
                uint32_t b0, b1, b2, b3;
                ldsm_x4(b0, b1, b2, b3, bbase + SW128(row * 128 + bo));
#pragma unroll
                for (int mi = 0; mi < 2; ++mi) {
                    mma16816(acc[mi][ni * 2],     afr[mi], b0, b2);
                    mma16816(acc[mi][ni * 2 + 1], afr[mi], b1, b3);
                }
            }
        }
    };

    {
        int ky, ao, bo, kx, ai;
        decode(0, ky, ao, bo, kx, ai);
        stageA(ky, ao, ai % 3);
        stageB(ky * K + kx, bo, 0);
        CP_COMMIT();
    }

    int kxc, aic;
    { int ky, ao, bo; decode(0, ky, ao, bo, kxc, aic); }

    for (int s = 0; s < NS; ++s) {
        if (s + 1 < NS) {
            int ky2, ao2, bo2, kx2, ai2;
            decode(s + 1, ky2, ao2, bo2, kx2, ai2);
            stageB(ky2 * K + kx2, bo2, (s + 1) % 3);
            if (ai2 != aic) stageA(ky2, ao2, ai2 % 3);
            CP_COMMIT();
            CP_WAIT(1);
            __syncthreads();
            consume(s, kxc, aic);
            kxc = kx2; aic = ai2;
        } else {
            CP_WAIT(0);
            __syncthreads();
            consume(s, kxc, aic);
        }
    }
    __syncthreads();

    if (tid < OCT) { sacc[tid] = 0.f; qacc[tid] = 0.f; }
    __syncthreads();

#pragma unroll
    for (int nj = 0; nj < NJ; ++nj) {
        int col = nw * (OCT / 2) + nj * 8 + (lane & 3) * 2;
        if (col < COUT) {
            float s0 = 0.f, s1 = 0.f, q0 = 0.f, q1 = 0.f;
#pragma unroll
            for (int mi = 0; mi < 2; ++mi) {
                int row = mw * 32 + mi * 16 + (lane >> 2);
                float d0 = acc[mi][nj][0], d1 = acc[mi][nj][1];
                float d2 = acc[mi][nj][2], d3 = acc[mi][nj][3];
                *(float2*)(out + (size_t)(p0 + row) * COUT + col)     = make_float2(d0, d1);
                *(float2*)(out + (size_t)(p0 + row + 8) * COUT + col) = make_float2(d2, d3);
                s0 += d0 + d2; s1 += d1 + d3;
                q0 += d0 * d0 + d2 * d2; q1 += d1 * d1 + d3 * d3;
            }
            atomicAdd(&sacc[col], s0);     atomicAdd(&sacc[col + 1], s1);
            atomicAdd(&qacc[col], q0);     atomicAdd(&qacc[col + 1], q1);
        }
    }
    __syncthreads();
    if (tid < OCT && tid < COUT) {
        atomicAdd(&stats[tid], sacc[tid]);
        atomicAdd(&stats[128 + tid], qacc[tid]);
    }
}

// ---------------- obj2 1x1 (48->20), in-kernel bnfin(bn4)+relu ---------------
__global__ __launch_bounds__(256) void obj2_kernel(
    const float* __restrict__ in, const float* __restrict__ w,
    const float* __restrict__ b,
    const float* __restrict__ g4, const float* __restrict__ b4,
    const float* __restrict__ stats, float* __restrict__ out)
{
    __shared__ float wst[48 * 20];
    __shared__ float bs[20];
    __shared__ float ss[48], sh[48];
    int tid = threadIdx.x;
    if (tid < 48) {
        float inv = 1.f / (float)NPIX;
        float mu  = stats[tid] * inv;
        float var = stats[128 + tid] * inv - mu * mu;
        float sc  = g4[tid] * rsqrtf(var + 1e-5f);
        ss[tid] = sc;
        sh[tid] = b4[tid] - mu * sc;
    }
    for (int i = tid; i < 48 * 20; i += 256) {
        int o = i / 48, ic = i - o * 48;
        wst[ic * 20 + o] = w[o * 48 + ic];
    }
    if (tid < 20) bs[tid] = b[tid];
    __syncthreads();

    int p = blockIdx.x * 256 + tid;
    int n = p >> 16, pix = p & 65535;
    const float* ip = in + (size_t)p * 48;
    u64 accp[10];
#pragma unroll
    for (int o = 0; o < 10; ++o) accp[o] = pack2f(bs[2 * o], bs[2 * o + 1]);
#pragma unroll
    for (int ic = 0; ic < 48; ++ic) {
        float v = fmaxf(ip[ic] * ss[ic] + sh[ic], 0.f);
        u64 vb = bcast2(v);
#pragma unroll
        for (int o = 0; o < 10; ++o) {
            u64 wp = *(const u64*)&wst[ic * 20 + 2 * o];
            accp[o] = ffma2(wp, vb, accp[o]);
        }
    }
#pragma unroll
    for (int o = 0; o < 10; ++o) {
        float2 f = unpk(accp[o]);
        out[((size_t)(n * NOBJ + 2 * o)     << 16) + pix] = f.x;
        out[((size_t)(n * NOBJ + 2 * o + 1) << 16) + pix] = f.y;
    }
}

// ---------------- launch ----------------
extern "C" void kernel_launch(void* const* d_in, const int* in_sizes, int n_in,
                              void* d_out, int out_size)
{
    const float* feats  = (const float*)d_in[0];
    const int*   masks  = (const int*)  d_in[1];
    const float* w_ih   = (const float*)d_in[2];
    const float* w_hh   = (const float*)d_in[3];
    const float* b_ih   = (const float*)d_in[4];
    const float* b_hh   = (const float*)d_in[5];
    const float* conv1w = (const float*)d_in[6];
    const float* bn1g   = (const float*)d_in[7];
    const float* bn1b   = (const float*)d_in[8];
    const float* conv2w = (const float*)d_in[9];
    const float* bn2g   = (const float*)d_in[10];
    const float* bn2b   = (const float*)d_in[11];
    const float* conv3w = (const float*)d_in[12];
    const float* bn3g   = (const float*)d_in[13];
    const float* bn3b   = (const float*)d_in[14];
    const float* obj1w  = (const float*)d_in[15];
    const float* bn4g   = (const float*)d_in[16];
    const float* bn4b   = (const float*)d_in[17];
    const float* obj2w  = (const float*)d_in[18];
    const float* obj2b  = (const float*)d_in[19];
    float* out = (float*)d_out;

    void *pany, *pstats, *pbA, *pbB, *phA, *phB, *pf16, *pact, *pw16, *pw16b, *pw16g;
    cudaGetSymbolAddress(&pany, g_any);
    cudaGetSymbolAddress(&pstats, g_stats);
    cudaGetSymbolAddress(&pbA, g_bufA);
    cudaGetSymbolAddress(&pbB, g_bufB);
    cudaGetSymbolAddress(&phA, g_hA);
    cudaGetSymbolAddress(&phB, g_hB);
    cudaGetSymbolAddress(&pf16, g_f16);
    cudaGetSymbolAddress(&pact, g_act16);
    cudaGetSymbolAddress(&pw16, g_w16);
    cudaGetSymbolAddress(&pw16b, g_w16b);
    cudaGetSymbolAddress(&pw16g, g_w16g);
    float* bA = (float*)pbA;
    float* bB = (float*)pbB;
    __half* hA = (__half*)phA;
    __half* hB = (__half*)phB;
    __half* f16 = (__half*)pf16;
    __half* act = (__half*)pact;
    __half* w16 = (__half*)pw16;
    __half* w16b = (__half*)pw16b;
    __half* w16g = (__half*)pw16g;
    float* stats = (float*)pstats;

    auto* g0 = gru_hmma<true>;
    auto* g1 = gru_hmma<false>;
    auto* c1 = conv_hmma<7, 2, 128, 128, 128, 1>;
    auto* c2 = conv_hmma<3, 2, 256, 64, 64, 3>;
    auto* c3 = conv_hmma<3, 1, 128, 64, 48, 3>;
    const int SM1 = 3 * (134 * 128) + 3 * 16384 + 128 * 8;   // 101632
    const int SM2 = 3 * (130 * 128) + 3 * 8192 + 64 * 8;     // 75008
    cudaFuncSetAttribute(g0, cudaFuncAttributeMaxDynamicSharedMemorySize, GRU_SMEM);
    cudaFuncSetAttribute(g1, cudaFuncAttributeMaxDynamicSharedMemorySize, GRU_SMEM);
    cudaFuncSetAttribute(c1, cudaFuncAttributeMaxDynamicSharedMemorySize, SM1);
    cudaFuncSetAttribute(c2, cudaFuncAttributeMaxDynamicSharedMemorySize, SM2);
    cudaFuncSetAttribute(c3, cudaFuncAttributeMaxDynamicSharedMemorySize, SM2);

    // launch order: memset, memset, w16gru_prep, f16feat, g0, g1 (#6 profiled)
    cudaMemsetAsync(pany, 0, sizeof(g_any));
    cudaMemsetAsync(pstats, 0, sizeof(g_stats));
    w16gru_prep<<<384, 256>>>(w_ih, w_hh, w16g);
    f16feat<<<16384, 256>>>(feats, f16);

    dim3 ggrid(1024, 4);
    g0<<<ggrid, 256, GRU_SMEM>>>(f16, masks, w16g, b_ih, b_hh, hA, hA, 0);
    g1<<<ggrid, 256, GRU_SMEM>>>(f16, masks, w16g, b_ih, b_hh, hA, hB, 1);
    g1<<<ggrid, 256, GRU_SMEM>>>(f16, masks, w16g, b_ih, b_hh, hB, hA, 2);
    g1<<<ggrid, 256, GRU_SMEM>>>(f16, masks, w16g, b_ih, b_hh, hA, hB, 3);

    // mask outputs + conv weight preps
    any_kernel<<<2048, 256>>>(masks);
    obs_kernel<<<512, 256>>>(masks, out + (size_t)NB * NOBJ * HW);
    w16prep<<<3136, 256>>>(conv1w, w16, 49, 128, 128, 128, 128);
    w16prep_hl<<<288, 256>>>(conv2w, w16b,          9, 64, 128, 64, 128);
    w16prep_hl<<<144, 256>>>(conv3w, w16b + 147456, 9, 64,  64, 48,  64);
    w16prep_hl<<<144, 256>>>(obj1w,  w16b + 221184, 9, 64,  64, 48,  48);

    // conv1 7x7 128->128
    c1<<<1024, 256, SM1>>>(hB, w16, bB, stats);

    // conv2 3x3 128->64 (hi/lo)
    bnrelu_hl<128, 128><<<8192, 256>>>(bB, act, bn1g, bn1b, stats);
    c2<<<1024, 256, SM2>>>(act, w16b, bA, stats + 256);

    // conv3 3x3 64->48 (hi/lo)
    bnrelu_hl<64, 64><<<4096, 256>>>(bA, act, bn2g, bn2b, stats + 256);
    c3<<<1024, 256, SM2>>>(act, w16b + 147456, bB, stats + 512);

    // obj1 3x3 48->48 (hi/lo)
    bnrelu_hl<48, 64><<<4096, 256>>>(bB, act, bn3g, bn3b, stats + 512);
    c3<<<1024, 256, SM2>>>(act, w16b + 221184, bA, stats + 768);

    // obj2 1x1 48->20 + bias (in-kernel bn4+relu)
    obj2_kernel<<<512, 256>>>(bA, obj2w, obj2b, bn4g, bn4b, stats + 768, out);
}

// round 17
// speedup vs baseline: 1.0441x; 1.0152x over previous
#include <cuda_runtime.h>
#include <cuda_fp16.h>
#include <cstdint>

#define EGO   64
#define MEM   128
#define NOBJ  20
#define HW    65536     // 256*256
#define NPIX  131072    // 2 * HW
#define NB    2
#define TT    4

typedef unsigned long long u64;

// ---------------- packed f32x2 helpers ----------------
__device__ __forceinline__ u64 bcast2(float x) {
    u64 r; asm("mov.b64 %0, {%1, %1};" : "=l"(r) : "f"(x)); return r;
}
__device__ __forceinline__ u64 pack2f(float x, float y) {
    u64 r; asm("mov.b64 %0, {%1, %2};" : "=l"(r) : "f"(x), "f"(y)); return r;
}
__device__ __forceinline__ u64 ffma2(u64 a, u64 b, u64 c) {
    u64 d; asm("fma.rn.f32x2 %0, %1, %2, %3;" : "=l"(d) : "l"(a), "l"(b), "l"(c)); return d;
}
__device__ __forceinline__ float2 unpk(u64 a) {
    float2 f; asm("mov.b64 {%0, %1}, %2;" : "=f"(f.x), "=f"(f.y) : "l"(a)); return f;
}

// ---------------- fast transcendentals ----------------
__device__ __forceinline__ float fast_sigmoid(float x) {
    float e; asm("ex2.approx.f32 %0, %1;" : "=f"(e) : "f"(-1.4426950408889634f * x));
    float r; asm("rcp.approx.f32 %0, %1;" : "=f"(r) : "f"(1.f + e));
    return r;
}
__device__ __forceinline__ float fast_tanh(float x) {
    float e; asm("ex2.approx.f32 %0, %1;" : "=f"(e) : "f"(2.8853900817779268f * x));
    float r; asm("rcp.approx.f32 %0, %1;" : "=f"(r) : "f"(1.f + e));
    return 1.f - 2.f * r;
}

// ---------------- smem / swizzle / mma / cp.async helpers ----------------
__device__ __forceinline__ uint32_t smem_u32(const void* p) {
    uint32_t a; asm("{ .reg .u64 t; cvta.to.shared.u64 t, %1; cvt.u32.u64 %0, t; }" : "=r"(a) : "l"(p));
    return a;
}
#define SW128(o) ((o) ^ (((o) >> 3) & 0x70))

__device__ __forceinline__ void ldsm_x4(uint32_t& r0, uint32_t& r1, uint32_t& r2, uint32_t& r3,
                                        uint32_t addr) {
    asm volatile("ldmatrix.sync.aligned.m8n8.x4.shared.b16 {%0,%1,%2,%3}, [%4];"
                 : "=r"(r0), "=r"(r1), "=r"(r2), "=r"(r3) : "r"(addr));
}
__device__ __forceinline__ void mma16816(float* c, const uint32_t* a, uint32_t b0, uint32_t b1) {
    asm volatile(
        "mma.sync.aligned.m16n8k16.row.col.f32.f16.f16.f32 "
        "{%0,%1,%2,%3}, {%4,%5,%6,%7}, {%8,%9}, {%0,%1,%2,%3};"
        : "+f"(c[0]), "+f"(c[1]), "+f"(c[2]), "+f"(c[3])
        : "r"(a[0]), "r"(a[1]), "r"(a[2]), "r"(a[3]), "r"(b0), "r"(b1));
}
__device__ __forceinline__ void cp16(uint32_t dst, const void* src) {
    asm volatile("cp.async.cg.shared.global [%0], [%1], 16;" :: "r"(dst), "l"(src));
}
__device__ __forceinline__ void cp16z(uint32_t dst, const void* src, int sz) {
    asm volatile("cp.async.cg.shared.global [%0], [%1], 16, %2;" :: "r"(dst), "l"(src), "r"(sz));
}
#define CP_COMMIT() asm volatile("cp.async.commit_group;" ::: "memory")
#define CP_WAIT(n)  asm volatile("cp.async.wait_group %0;" :: "n"(n) : "memory")

// ---------------- static scratch ----------------
__device__ __half g_hA[(size_t)NPIX * 128];
__device__ __half g_hB[(size_t)NPIX * 128];
__device__ __half g_f16[(size_t)NPIX * TT * 64];  // fp16 features
__device__ __half g_act16[(size_t)NPIX * 256];
__device__ float  g_bufA[(size_t)NPIX * 128];
__device__ float  g_bufB[(size_t)NPIX * 128];
__device__ __half g_w16[49 * 128 * 128];         // conv1
__device__ __half g_w16b[300000];                // conv2 @0, conv3 @147456, obj1 @221184
__device__ __half g_w16g[4 * 3 * 128 * 64];      // GRU
__device__ int    g_any[8];
__device__ float  g_stats[1024];                 // 4 segments of 256

// ---------------- any / observed ----------------
__global__ void any_kernel(const int* __restrict__ masks) {
    int idx = blockIdx.x * blockDim.x + threadIdx.x;
    int v = masks[idx];
    unsigned b = __ballot_sync(0xffffffffu, v > 0);
    if ((threadIdx.x & 31) == 0 && b)
        atomicOr(&g_any[idx >> 16], 1);
}
__global__ void obs_kernel(const int* __restrict__ masks, float* __restrict__ outobs) {
    int idx = blockIdx.x * blockDim.x + threadIdx.x;
    int n = idx >> 16, pix = idx & 65535;
    int s = 0;
#pragma unroll
    for (int t = 0; t < TT; ++t)
        s += masks[((n * TT + t) << 16) + pix] * g_any[n * TT + t];
    outobs[idx] = (float)s;
}

// ---------------- feats fp32 -> fp16 ----------------
__global__ void f16feat(const float* __restrict__ in, __half* __restrict__ out) {
    size_t i = ((size_t)blockIdx.x * 256 + threadIdx.x) * 8;
    float4 a = *(const float4*)(in + i);
    float4 b = *(const float4*)(in + i + 4);
    __half2 h[4] = { __floats2half2_rn(a.x, a.y), __floats2half2_rn(a.z, a.w),
                     __floats2half2_rn(b.x, b.y), __floats2half2_rn(b.z, b.w) };
    *(uint4*)(out + i) = *(const uint4*)h;
}

// ---------------- GRU weight prep (gate-grouped columns) ----------------
__global__ void w16gru_prep(const float* __restrict__ wih, const float* __restrict__ whh,
                            __half* __restrict__ o) {
    int i = blockIdx.x * 256 + threadIdx.x;
    if (i >= 4 * 3 * 128 * 64) return;
    int bb = i / 24576; int r = i - bb * 24576;
    int c  = r / 8192;  int r2 = r - c * 8192;
    int row = r2 >> 6;  int kk = r2 & 63;
    int g4 = row >> 5, ul = row & 31;
    int gu = bb * 32 + ul;
    float v = 0.f;
    if (g4 == 0)      v = (c == 0) ? wih[(      gu) * 64 + kk] : whh[(      gu) * 128 + (c - 1) * 64 + kk];
    else if (g4 == 1) v = (c == 0) ? wih[(128 + gu) * 64 + kk] : whh[(128 + gu) * 128 + (c - 1) * 64 + kk];
    else if (g4 == 2) v = (c == 0) ? wih[(256 + gu) * 64 + kk] : 0.f;
    else              v = (c == 0) ? 0.f : whh[(256 + gu) * 128 + (c - 1) * 64 + kk];
    o[i] = __float2half_rn(v);
}

// ---------------- GRU step via HMMA (balanced gate tiles) ----------------
// Column tiles (16 cols each): 0,1=r  2,3=z  4,5=nx  6,7=nh.
// nw0 owns {0, 1, nx0|nh0}; nw1 owns {2, 3, nx1|nh1} -> 3 dob/warp/kk, balanced.
#define GRU_SMEM (98304 + 768 + 32 + 512 + 512)
#define GSTR 132

template<bool FIRST>
__global__ __launch_bounds__(256, 2) void gru_hmma(
    const __half* __restrict__ f16, const int* __restrict__ masks,
    const __half* __restrict__ w16g,
    const float* __restrict__ b_ih, const float* __restrict__ b_hh,
    const __half* __restrict__ hin, __half* __restrict__ hout, int t)
{
    extern __shared__ char sm[];
    float* gbuf = (float*)sm;
    float* sbias = (float*)(sm + 98304);
    int* wcnt  = (int*)(sm + 98304 + 768);
    int* cnts  = (int*)(sm + 98304 + 768 + 16);
    int* clist = (int*)(sm + 98304 + 768 + 32);
    int* ulist = (int*)(sm + 98304 + 768 + 32 + 512);

    int tid = threadIdx.x;
    int lane = tid & 31, wrp = tid >> 5;
    int mw = wrp >> 1, nw = wrp & 1;
    int p0 = blockIdx.x * 128;
    int bb = blockIdx.y;
    int ub = bb * 32;
    int n = p0 >> 16, pix0 = p0 & 65535;
    uint32_t sbase = smem_u32(sm);

    const int* mrow = masks + ((size_t)(n * TT + t) << 16) + pix0;

    const int CH = FIRST ? 1 : 3;
    int px = tid >> 1, sg = tid & 1;

    // ---- stage everything via cp.async ----
    {
        int sr = tid >> 1, h2 = tid & 1;
#pragma unroll
        for (int c = 0; c < 3; ++c) {
            if (c >= CH) break;
            const __half* src = w16g + ((size_t)((bb * 3 + c) * 128 + sr)) * 64 + h2 * 32;
            uint32_t base = sbase + 49152 + c * 16384;
#pragma unroll
            for (int j = 0; j < 4; ++j) {
                uint32_t bo = (uint32_t)sr * 128 + h2 * 64 + j * 16;
                cp16(base + SW128(bo), src + j * 8);
            }
        }
    }
    {
        const __half* src = f16 + ((size_t)(n * TT + t) * HW + pix0 + px) * 64 + sg * 32;
#pragma unroll
        for (int j = 0; j < 4; ++j) {
            uint32_t bo = (uint32_t)px * 128 + sg * 64 + j * 16;
            cp16(sbase + SW128(bo), src + j * 8);
        }
    }
    if (!FIRST) {
#pragma unroll
        for (int c = 1; c < 3; ++c) {
            const __half* src = hin + ((size_t)(p0 + px)) * 128 + (c - 1) * 64 + sg * 32;
            uint32_t base = sbase + c * 16384;
#pragma unroll
            for (int j = 0; j < 4; ++j) {
                uint32_t bo = (uint32_t)px * 128 + sg * 64 + j * 16;
                cp16(base + SW128(bo), src + j * 8);
            }
        }
    }
    CP_COMMIT();

    int mv = 0; int posm = 0;
    if (tid < 128) {
        mv = mrow[tid] > 0;
        unsigned bal = __ballot_sync(0xffffffffu, mv);
        posm = __popc(bal & ((1u << lane) - 1));
        if (lane == 0) wcnt[tid >> 5] = __popc(bal);
    }
    if (tid < 96) {
        int g = tid >> 5, u = tid & 31;
        sbias[tid] = b_ih[g * 128 + ub + u];
    } else if (tid < 192) {
        int t2 = tid - 96;
        int g = t2 >> 5, u = t2 & 31;
        sbias[tid] = b_hh[g * 128 + ub + u];
    }

    CP_WAIT(0);
    __syncthreads();
    if (tid < 128) {
        int w = tid >> 5;
        int off = 0;
#pragma unroll
        for (int j = 0; j < 4; ++j) if (j < w) off += wcnt[j];
        if (mv) clist[off + posm] = tid;
        else    ulist[32 * w - off + lane - posm] = tid;
        if (tid == 0) cnts[0] = wcnt[0] + wcnt[1] + wcnt[2] + wcnt[3];
    }

    // per-warp tile assignment: base tiles (always active) + nx/nh tile
    const int tb0 = (nw == 0) ? 0 : 2;   // tiles tb0, tb0+1 : r-pair or z-pair
    const int tlx = (nw == 0) ? 4 : 5;   // nx tile (chunk 0)
    const int tlh = (nw == 0) ? 6 : 7;   // nh tile (chunks 1,2)

    float acc[2][8][4];
#pragma unroll
    for (int mi = 0; mi < 2; ++mi)
#pragma unroll
        for (int nj = 0; nj < 8; ++nj)
#pragma unroll
            for (int e = 0; e < 4; ++e) acc[mi][nj][e] = 0.f;

#pragma unroll
    for (int c = 0; c < 3; ++c) {
        if (c >= CH) break;
        uint32_t abase = sbase + c * 16384;
        uint32_t bbase = sbase + 49152 + c * 16384;
#pragma unroll
        for (int kk = 0; kk < 4; ++kk) {
            uint32_t bo = kk * 32 + ((lane >> 4) << 4);
            uint32_t afr[2][4];
#pragma unroll
            for (int mi = 0; mi < 2; ++mi) {
                uint32_t row = mw * 32 + mi * 16 + (lane & 15);
                ldsm_x4(afr[mi][0], afr[mi][1], afr[mi][2], afr[mi][3],
                        abase + SW128(row * 128 + bo));
            }
            auto dob = [&](int tl, int pj) {
                uint32_t row = (uint32_t)tl * 16 + (lane & 15);
                uint32_t b0, b1, b2, b3;
                ldsm_x4(b0, b1, b2, b3, bbase + SW128(row * 128 + bo));
#pragma unroll
                for (int mi = 0; mi < 2; ++mi) {
                    mma16816(acc[mi][pj],     afr[mi], b0, b2);
                    mma16816(acc[mi][pj + 1], afr[mi], b1, b3);
                }
            };
            dob(tb0, 0);
            dob(tb0 + 1, 2);
            if (c == 0) dob(tlx, 4);
            else        dob(tlh, 6);
        }
    }
    __syncthreads();

    // ---- transpose accums to gbuf [px][GSTR]; tile->col mapping per warp ----
    {
        int tls[4] = { tb0, tb0 + 1, tlx, tlh };
#pragma unroll
        for (int tI = 0; tI < 4; ++tI) {
#pragma unroll
            for (int e = 0; e < 2; ++e) {
                int nj = tI * 2 + e;
                int col = tls[tI] * 16 + e * 8 + (lane & 3) * 2;
#pragma unroll
                for (int mi = 0; mi < 2; ++mi) {
                    int row = mw * 32 + mi * 16 + (lane >> 2);
                    *(float2*)&gbuf[row * GSTR + col]       = make_float2(acc[mi][nj][0], acc[mi][nj][1]);
                    *(float2*)&gbuf[(row + 8) * GSTR + col] = make_float2(acc[mi][nj][2], acc[mi][nj][3]);
                }
            }
        }
    }
    __syncthreads();

    int cnt = cnts[0];
    for (int i = tid; i < 2 * cnt; i += 256) {
        int pxl = clist[i >> 1];
        int half = i & 1;
        __half hold[16];
        if (!FIRST) {
            const __half* hp = hin + ((size_t)(p0 + pxl)) * 128 + ub + half * 16;
            *(uint4*)&hold[0] = *(const uint4*)hp;
            *(uint4*)&hold[8] = *(const uint4*)(hp + 8);
        }
        __half hnew[16];
#pragma unroll
        for (int ug = 0; ug < 4; ++ug) {
            int cb = half * 16 + ug * 4;
            float4 rr = *(float4*)&gbuf[pxl * GSTR + cb];
            float4 zz = *(float4*)&gbuf[pxl * GSTR + 32 + cb];
            float4 xx = *(float4*)&gbuf[pxl * GSTR + 64 + cb];
            float4 hh4 = *(float4*)&gbuf[pxl * GSTR + 96 + cb];
            float rv[4] = { rr.x, rr.y, rr.z, rr.w };
            float zv[4] = { zz.x, zz.y, zz.z, zz.w };
            float xv[4] = { xx.x, xx.y, xx.z, xx.w };
            float hv4[4] = { hh4.x, hh4.y, hh4.z, hh4.w };
#pragma unroll
            for (int e = 0; e < 4; ++e) {
                int ul = cb + e;
                float r = fast_sigmoid(rv[e] + sbias[ul] + sbias[96 + ul]);
                float z = fast_sigmoid(zv[e] + sbias[32 + ul] + sbias[128 + ul]);
                float nv = fast_tanh(xv[e] + sbias[64 + ul] + r * (hv4[e] + sbias[160 + ul]));
                float ho = FIRST ? 0.f : __half2float(hold[ug * 4 + e]);
                float hv = nv + z * (ho - nv);
                hnew[ug * 4 + e] = __float2half_rn(hv);
            }
        }
        __half* op = hout + ((size_t)(p0 + pxl)) * 128 + ub + half * 16;
        *(uint4*)op       = *(const uint4*)&hnew[0];
        *(uint4*)(op + 8) = *(const uint4*)&hnew[8];
    }
    int un = 128 - cnt;
    for (int i = tid; i < 2 * un; i += 256) {
        int pxl = ulist[i >> 1];
        int half = i & 1;
        __half* op = hout + ((size_t)(p0 + pxl)) * 128 + ub + half * 16;
        if (FIRST) {
            uint4 z = make_uint4(0, 0, 0, 0);
            *(uint4*)op = z; *(uint4*)(op + 8) = z;
        } else {
            const __half* hp = hin + ((size_t)(p0 + pxl)) * 128 + ub + half * 16;
            *(uint4*)op       = *(const uint4*)hp;
            *(uint4*)(op + 8) = *(const uint4*)(hp + 8);
        }
    }
}

// ---------------- bn+relu (in-kernel bnfin) f32 -> hi/lo fp16 ----------------
template<int CIN, int CHI>
__global__ void bnrelu_hl(const float* __restrict__ in, __half* __restrict__ out,
                          const float* __restrict__ g, const float* __restrict__ b,
                          const float* __restrict__ stats) {
    __shared__ float ss[CIN], sh[CIN];
    int tid = threadIdx.x;
    if (tid < CIN) {
        float inv = 1.f / (float)NPIX;
        float mu  = stats[tid] * inv;
        float var = stats[128 + tid] * inv - mu * mu;
        float sc  = g[tid] * rsqrtf(var + 1e-5f);
        ss[tid] = sc;
        sh[tid] = b[tid] - mu * sc;
    }
    __syncthreads();

    int i = blockIdx.x * 256 + tid;
    int px = i / (CHI / 8);
    int c0 = (i % (CHI / 8)) * 8;
    __half2 hi[4], lo[4];
#pragma unroll
    for (int j = 0; j < 4; ++j) {
        int c = c0 + 2 * j;
        float v0 = 0.f, v1 = 0.f;
        if (c < CIN) {
            float2 v = *(const float2*)(in + (size_t)px * CIN + c);
            v0 = fmaxf(v.x * ss[c] + sh[c], 0.f);
            v1 = fmaxf(v.y * ss[c + 1] + sh[c + 1], 0.f);
        }
        __half h0 = __float2half_rn(v0), h1 = __float2half_rn(v1);
        hi[j] = __halves2half2(h0, h1);
        lo[j] = __floats2half2_rn(v0 - __half2float(h0), v1 - __half2float(h1));
    }
    *(uint4*)(out + (size_t)px * (2 * CHI) + c0)       = *(const uint4*)hi;
    *(uint4*)(out + (size_t)px * (2 * CHI) + CHI + c0) = *(const uint4*)lo;
}

// ---------------- weight prep ----------------
__global__ void w16prep(const float* __restrict__ w, __half* __restrict__ o,
                        int NTAP, int OCT, int ICP, int Cout, int Cin) {
    int i = blockIdx.x * 256 + threadIdx.x;
    if (i >= NTAP * OCT * ICP) return;
    int tap = i / (OCT * ICP);
    int r = i - tap * (OCT * ICP);
    int oc = r / ICP, ic = r - oc * ICP;
    float v = (oc < Cout && ic < Cin) ? w[((size_t)oc * Cin + ic) * NTAP + tap] : 0.f;
    o[i] = __float2half_rn(v);
}
__global__ void w16prep_hl(const float* __restrict__ w, __half* __restrict__ o,
                           int NTAP, int OCT, int ICP, int Cout, int Cin) {
    int i = blockIdx.x * 256 + threadIdx.x;
    if (i >= NTAP * OCT * ICP) return;
    int tap = i / (OCT * ICP);
    int r = i - tap * (OCT * ICP);
    int oc = r / ICP, ic = r - oc * ICP;
    float v = (oc < Cout && ic < Cin) ? w[((size_t)oc * Cin + ic) * NTAP + tap] : 0.f;
    __half h = __float2half_rn(v);
    size_t base = ((size_t)tap * OCT + oc) * (2 * ICP);
    o[base + ic] = h;
    o[base + ICP + ic] = __float2half_rn(v - __half2float(h));
}

// ---------------- HMMA implicit-GEMM conv: cp.async, 3-slot ring -------------
template<int K, int ICH, int CINP, int OCT, int COUT, int PHASES>
__global__ __launch_bounds__(256) void conv_hmma(
    const __half* __restrict__ in, const __half* __restrict__ w16,
    float* __restrict__ out, float* __restrict__ stats)
{
    constexpr int PAD = K / 2;
    constexpr int RWIN = 128 + 2 * PAD;
    constexpr int NS = K * K * PHASES * ICH;
    constexpr int BW = (PHASES == 3 ? 2 : 1) * ICH * 64;
    constexpr int ABYTES = RWIN * 128;
    constexpr int BBYTES = OCT * 128;
    constexpr int NJ = OCT / 16;
    constexpr int NI2 = NJ / 2;
    constexpr int BLK = K * PHASES;
    constexpr int BPER = (OCT * 8) / 256;

    extern __shared__ __align__(16) char sm[];
    float* sacc = (float*)(sm + 3 * ABYTES + 3 * BBYTES);
    float* qacc = sacc + OCT;

    int tid = threadIdx.x;
    int lane = tid & 31, wrp = tid >> 5;
    int mw = wrp >> 1, nw = wrp & 1;
    int p0 = blockIdx.x * 128;
    int n = p0 >> 16;
    int y = (p0 >> 8) & 255;
    int x0 = p0 & 255;
    uint32_t sbase = smem_u32(sm);

    float acc[2][NJ][4];
#pragma unroll
    for (int mi = 0; mi < 2; ++mi)
#pragma unroll
        for (int nj = 0; nj < NJ; ++nj)
#pragma unroll
            for (int e = 0; e < 4; ++e) acc[mi][nj][e] = 0.f;

    auto decode = [&](int s, int& ky, int& aoff, int& boff, int& kx, int& a_id) {
        int t0 = s / (BLK * ICH);
        int t1 = s - t0 * BLK * ICH;
        int i  = t1 / BLK;
        int u  = t1 - i * BLK;
        int seg = u / K;
        kx = u - seg * K;
        ky = t0;
        aoff = (seg == 2) ? ICH + i : i;
        boff = (seg == 1) ? ICH + i : i;
        a_id = (PHASES == 3) ? ((t0 * ICH + i) * 2 + (seg == 2 ? 1 : 0))
                             : (t0 * ICH + i);
    };

    auto stageA = [&](int ky, int aoff, int slot) {
        uint32_t base = sbase + slot * ABYTES;
        int gy = y + ky - PAD;
        int hh = tid & 1;
        bool rowok = (unsigned)gy < 256u;
        for (int r = tid >> 1; r < RWIN; r += 128) {
            int gx = x0 + r - PAD;
            bool ok = rowok && (unsigned)gx < 256u;
            const __half* src = in + ((size_t)((n * 256 + (ok ? gy : 0)) * 256 + (ok ? gx : 0))) * CINP
                                + aoff * 64 + hh * 32;
            int sz = ok ? 16 : 0;
#pragma unroll
            for (int j = 0; j < 4; ++j) {
                uint32_t bo = (uint32_t)r * 128 + hh * 64 + j * 16;
                cp16z(base + SW128(bo), src + j * 8, sz);
            }
        }
    };
    auto stageB = [&](int tap, int boff, int slot) {
        uint32_t base = sbase + 3 * ABYTES + slot * BBYTES;
#pragma unroll
        for (int j = 0; j < BPER; ++j) {
            int idx = tid * BPER + j;
            int row = idx >> 3, q = idx & 7;
            const __half* src = w16 + ((size_t)tap * OCT + row) * BW + boff * 64 + q * 8;
            uint32_t bo = (uint32_t)row * 128 + q * 16;
            cp16(base + SW128(bo), src);
        }
    };
    auto consume = [&](int s_, int kx_, int aid_) {
        uint32_t abase = sbase + (aid_ % 3) * ABYTES;
        uint32_t bbase = sbase + 3 * ABYTES + (s_ % 3) * BBYTES;
#pragma unroll
        for (int kk = 0; kk < 4; ++kk) {
            uint32_t bo = kk * 32 + ((lane >> 4) << 4);
            uint32_t afr[2][4];
#pragma unroll
            for (int mi = 0; mi < 2; ++mi) {
                uint32_t row = mw * 32 + mi * 16 + (lane & 15) + kx_;
                ldsm_x4(afr[mi][0], afr[mi][1], afr[mi][2], afr[mi][3],
                        abase + SW128(row * 128 + bo));
            }
#pragma unroll
            for (int ni = 0; ni < NI2; ++ni) {
                uint32_t row = nw * (OCT / 2) + ni * 16 + (lane & 15);
                uint32_t b0, b1, b2, b3;
                ldsm_x4(b0, b1, b2, b3, bbase + SW128(row * 128 + bo));
#pragma unroll
                for (int mi = 0; mi < 2; ++mi) {
                    mma16816(acc[mi][ni * 2],     afr[mi], b0, b2);
                    mma16816(acc[mi][ni * 2 + 1], afr[mi], b1, b3);
                }
            }
        }
    };

    {
        int ky, ao, bo, kx, ai;
        decode(0, ky, ao, bo, kx, ai);
        stageA(ky, ao, ai % 3);
        stageB(ky * K + kx, bo, 0);
        CP_COMMIT();
    }

    int kxc, aic;
    { int ky, ao, bo; decode(0, ky, ao, bo, kxc, aic); }

    for (int s = 0; s < NS; ++s) {
        if (s + 1 < NS) {
            int ky2, ao2, bo2, kx2, ai2;
            decode(s + 1, ky2, ao2, bo2, kx2, ai2);
            stageB(ky2 * K + kx2, bo2, (s + 1) % 3);
            if (ai2 != aic) stageA(ky2, ao2, ai2 % 3);
            CP_COMMIT();
            CP_WAIT(1);
            __syncthreads();
            consume(s, kxc, aic);
            kxc = kx2; aic = ai2;
        } else {
            CP_WAIT(0);
            __syncthreads();
            consume(s, kxc, aic);
        }
    }
    __syncthreads();

    if (tid < OCT) { sacc[tid] = 0.f; qacc[tid] = 0.f; }
    __syncthreads();

#pragma unroll
    for (int nj = 0; nj < NJ; ++nj) {
        int col = nw * (OCT / 2) + nj * 8 + (lane & 3) * 2;
        if (col < COUT) {
            float s0 = 0.f, s1 = 0.f, q0 = 0.f, q1 = 0.f;
#pragma unroll
            for (int mi = 0; mi < 2; ++mi) {
                int row = mw * 32 + mi * 16 + (lane >> 2);
                float d0 = acc[mi][nj][0], d1 = acc[mi][nj][1];
                float d2 = acc[mi][nj][2], d3 = acc[mi][nj][3];
                *(float2*)(out + (size_t)(p0 + row) * COUT + col)     = make_float2(d0, d1);
                *(float2*)(out + (size_t)(p0 + row + 8) * COUT + col) = make_float2(d2, d3);
                s0 += d0 + d2; s1 += d1 + d3;
                q0 += d0 * d0 + d2 * d2; q1 += d1 * d1 + d3 * d3;
            }
            atomicAdd(&sacc[col], s0);     atomicAdd(&sacc[col + 1], s1);
            atomicAdd(&qacc[col], q0);     atomicAdd(&qacc[col + 1], q1);
        }
    }
    __syncthreads();
    if (tid < OCT && tid < COUT) {
        atomicAdd(&stats[tid], sacc[tid]);
        atomicAdd(&stats[128 + tid], qacc[tid]);
    }
}

// ---------------- obj2 1x1 (48->20), in-kernel bnfin(bn4)+relu ---------------
__global__ __launch_bounds__(256) void obj2_kernel(
    const float* __restrict__ in, const float* __restrict__ w,
    const float* __restrict__ b,
    const float* __restrict__ g4, const float* __restrict__ b4,
    const float* __restrict__ stats, float* __restrict__ out)
{
    __shared__ float wst[48 * 20];
    __shared__ float bs[20];
    __shared__ float ss[48], sh[48];
    int tid = threadIdx.x;
    if (tid < 48) {
        float inv = 1.f / (float)NPIX;
        float mu  = stats[tid] * inv;
        float var = stats[128 + tid] * inv - mu * mu;
        float sc  = g4[tid] * rsqrtf(var + 1e-5f);
        ss[tid] = sc;
        sh[tid] = b4[tid] - mu * sc;
    }
    for (int i = tid; i < 48 * 20; i += 256) {
        int o = i / 48, ic = i - o * 48;
        wst[ic * 20 + o] = w[o * 48 + ic];
    }
    if (tid < 20) bs[tid] = b[tid];
    __syncthreads();

    int p = blockIdx.x * 256 + tid;
    int n = p >> 16, pix = p & 65535;
    const float* ip = in + (size_t)p * 48;
    u64 accp[10];
#pragma unroll
    for (int o = 0; o < 10; ++o) accp[o] = pack2f(bs[2 * o], bs[2 * o + 1]);
#pragma unroll
    for (int ic = 0; ic < 48; ++ic) {
        float v = fmaxf(ip[ic] * ss[ic] + sh[ic], 0.f);
        u64 vb = bcast2(v);
#pragma unroll
        for (int o = 0; o < 10; ++o) {
            u64 wp = *(const u64*)&wst[ic * 20 + 2 * o];
            accp[o] = ffma2(wp, vb, accp[o]);
        }
    }
#pragma unroll
    for (int o = 0; o < 10; ++o) {
        float2 f = unpk(accp[o]);
        out[((size_t)(n * NOBJ + 2 * o)     << 16) + pix] = f.x;
        out[((size_t)(n * NOBJ + 2 * o + 1) << 16) + pix] = f.y;
    }
}

// ---------------- launch ----------------
extern "C" void kernel_launch(void* const* d_in, const int* in_sizes, int n_in,
                              void* d_out, int out_size)
{
    const float* feats  = (const float*)d_in[0];
    const int*   masks  = (const int*)  d_in[1];
    const float* w_ih   = (const float*)d_in[2];
    const float* w_hh   = (const float*)d_in[3];
    const float* b_ih   = (const float*)d_in[4];
    const float* b_hh   = (const float*)d_in[5];
    const float* conv1w = (const float*)d_in[6];
    const float* bn1g   = (const float*)d_in[7];
    const float* bn1b   = (const float*)d_in[8];
    const float* conv2w = (const float*)d_in[9];
    const float* bn2g   = (const float*)d_in[10];
    const float* bn2b   = (const float*)d_in[11];
    const float* conv3w = (const float*)d_in[12];
    const float* bn3g   = (const float*)d_in[13];
    const float* bn3b   = (const float*)d_in[14];
    const float* obj1w  = (const float*)d_in[15];
    const float* bn4g   = (const float*)d_in[16];
    const float* bn4b   = (const float*)d_in[17];
    const float* obj2w  = (const float*)d_in[18];
    const float* obj2b  = (const float*)d_in[19];
    float* out = (float*)d_out;

    void *pany, *pstats, *pbA, *pbB, *phA, *phB, *pf16, *pact, *pw16, *pw16b, *pw16g;
    cudaGetSymbolAddress(&pany, g_any);
    cudaGetSymbolAddress(&pstats, g_stats);
    cudaGetSymbolAddress(&pbA, g_bufA);
    cudaGetSymbolAddress(&pbB, g_bufB);
    cudaGetSymbolAddress(&phA, g_hA);
    cudaGetSymbolAddress(&phB, g_hB);
    cudaGetSymbolAddress(&pf16, g_f16);
    cudaGetSymbolAddress(&pact, g_act16);
    cudaGetSymbolAddress(&pw16, g_w16);
    cudaGetSymbolAddress(&pw16b, g_w16b);
    cudaGetSymbolAddress(&pw16g, g_w16g);
    float* bA = (float*)pbA;
    float* bB = (float*)pbB;
    __half* hA = (__half*)phA;
    __half* hB = (__half*)phB;
    __half* f16 = (__half*)pf16;
    __half* act = (__half*)pact;
    __half* w16 = (__half*)pw16;
    __half* w16b = (__half*)pw16b;
    __half* w16g = (__half*)pw16g;
    float* stats = (float*)pstats;

    auto* g0 = gru_hmma<true>;
    auto* g1 = gru_hmma<false>;
    auto* c1 = conv_hmma<7, 2, 128, 128, 128, 1>;
    auto* c2 = conv_hmma<3, 2, 256, 64, 64, 3>;
    auto* c3 = conv_hmma<3, 1, 128, 64, 48, 3>;
    const int SM1 = 3 * (134 * 128) + 3 * 16384 + 128 * 8;   // 101632
    const int SM2 = 3 * (130 * 128) + 3 * 8192 + 64 * 8;     // 75008
    cudaFuncSetAttribute(g0, cudaFuncAttributeMaxDynamicSharedMemorySize, GRU_SMEM);
    cudaFuncSetAttribute(g1, cudaFuncAttributeMaxDynamicSharedMemorySize, GRU_SMEM);
    cudaFuncSetAttribute(c1, cudaFuncAttributeMaxDynamicSharedMemorySize, SM1);
    cudaFuncSetAttribute(c2, cudaFuncAttributeMaxDynamicSharedMemorySize, SM2);
    cudaFuncSetAttribute(c3, cudaFuncAttributeMaxDynamicSharedMemorySize, SM2);

    // launch order: memset, memset, w16gru_prep, f16feat, g0, g1 (#6 profiled)
    cudaMemsetAsync(pany, 0, sizeof(g_any));
    cudaMemsetAsync(pstats, 0, sizeof(g_stats));
    w16gru_prep<<<384, 256>>>(w_ih, w_hh, w16g);
    f16feat<<<16384, 256>>>(feats, f16);

    dim3 ggrid(1024, 4);
    g0<<<ggrid, 256, GRU_SMEM>>>(f16, masks, w16g, b_ih, b_hh, hA, hA, 0);
    g1<<<ggrid, 256, GRU_SMEM>>>(f16, masks, w16g, b_ih, b_hh, hA, hB, 1);
    g1<<<ggrid, 256, GRU_SMEM>>>(f16, masks, w16g, b_ih, b_hh, hB, hA, 2);
    g1<<<ggrid, 256, GRU_SMEM>>>(f16, masks, w16g, b_ih, b_hh, hA, hB, 3);

    // mask outputs + conv weight preps
    any_kernel<<<2048, 256>>>(masks);
    obs_kernel<<<512, 256>>>(masks, out + (size_t)NB * NOBJ * HW);
    w16prep<<<3136, 256>>>(conv1w, w16, 49, 128, 128, 128, 128);
    w16prep_hl<<<288, 256>>>(conv2w, w16b,          9, 64, 128, 64, 128);
    w16prep_hl<<<144, 256>>>(conv3w, w16b + 147456, 9, 64,  64, 48,  64);
    w16prep_hl<<<144, 256>>>(obj1w,  w16b + 221184, 9, 64,  64, 48,  48);

    // conv1 7x7 128->128
    c1<<<1024, 256, SM1>>>(hB, w16, bB, stats);

    // conv2 3x3 128->64 (hi/lo)
    bnrelu_hl<128, 128><<<8192, 256>>>(bB, act, bn1g, bn1b, stats);
    c2<<<1024, 256, SM2>>>(act, w16b, bA, stats + 256);

    // conv3 3x3 64->48 (hi/lo)
    bnrelu_hl<64, 64><<<4096, 256>>>(bA, act, bn2g, bn2b, stats + 256);
    c3<<<1024, 256, SM2>>>(act, w16b + 147456, bB, stats + 512);

    // obj1 3x3 48->48 (hi/lo)
    bnrelu_hl<48, 64><<<4096, 256>>>(bB, act, bn3g, bn3b, stats + 512);
    c3<<<1024, 256, SM2>>>(act, w16b + 221184, bA, stats + 768);

    // obj2 1x1 48->20 + bias (in-kernel bn4+relu)
    obj2_kernel<<<512, 256>>>(bA, obj2w, obj2b, bn4g, bn4b, stats + 768, out);
}